// round 6
// baseline (speedup 1.0000x reference)
#include <cuda_runtime.h>
#include <cuda_bf16.h>
#include <stdint.h>
#include <math.h>

#define N_NODES 10000
#define N_EDGES 160000
#define BATCH 4
#define T_STEPS 16
#define HID 64
#define M_PAD  40064             // 313 * 128
#define KDIM 208                 // 13 * 16
#define NKS 13

typedef uint32_t u32;

// ---------------- device scratch ----------------
__device__ float g_h [M_PAD*HID];
__device__ float g_z [M_PAD*HID];
__device__ float g_rh[M_PAD*HID];
__device__ float g_deg_out[N_NODES], g_deg_in[N_NODES];
__device__ int   g_cntF[N_NODES], g_cntB[N_NODES];
__device__ int   g_offF[N_NODES+1], g_offB[N_NODES+1];
__device__ int   g_srcF[N_EDGES], g_srcB[N_EDGES];
__device__ float g_wF[N_EDGES],  g_wB[N_EDGES];
// Prepacked B fragment tables: [ks][split][natom][lane] -> uint2 (b0,b1 of m16n8k16)
__device__ uint2 g_BfZr[NKS*2*16*32];
__device__ uint2 g_BfC [NKS*2*8*32];
__device__ float g_bzr[128], g_bh[64];

__device__ __forceinline__ u32 smem_u32(const void* p) {
    u32 a;
    asm("{ .reg .u64 t; cvta.to.shared.u64 t, %1; cvt.u32.u64 %0, t; }" : "=r"(a) : "l"(p));
    return a;
}

// ---------------- prep 1: single-block histogram + degree + scan ----------------
// dynamic smem: cF[10240] cB[10240] (int), dF[10240] dB[10240] (float)
__global__ void prep_scan(const int* __restrict__ ei, const float* __restrict__ ew) {
    extern __shared__ int sm[];
    int*   cF = sm;
    int*   cB = sm + 10240;
    float* dF = (float*)(sm + 20480);
    float* dB = (float*)(sm + 30720);
    __shared__ int sb[1024];
    int t = threadIdx.x;

    for (int i = t; i < 10240; i += 1024) { cF[i]=0; cB[i]=0; dF[i]=0.f; dB[i]=0.f; }
    __syncthreads();

    for (int e = t; e < N_EDGES; e += 1024) {
        int r = ei[e], c = ei[N_EDGES + e];
        float w = ew[e];
        atomicAdd(&cF[r], 1);
        atomicAdd(&cB[c], 1);
        atomicAdd(&dF[r], w);
        atomicAdd(&dB[c], w);
    }
    __syncthreads();

    for (int i = t; i < N_NODES; i += 1024) {
        g_deg_out[i] = dF[i];
        g_deg_in [i] = dB[i];
        g_cntF[i] = 0;
        g_cntB[i] = 0;
    }

    // exclusive scans: cF -> g_offF, cB -> g_offB
    for (int pass = 0; pass < 2; pass++) {
        const int* cnt = pass == 0 ? cF : cB;
        int*       off = pass == 0 ? g_offF : g_offB;
        int carry = 0;
        for (int base = 0; base < N_NODES; base += 1024) {
            int v = (base + t < N_NODES) ? cnt[base + t] : 0;
            sb[t] = v; __syncthreads();
            for (int o = 1; o < 1024; o <<= 1) {
                int y = (t >= o) ? sb[t - o] : 0;
                __syncthreads();
                sb[t] += y;
                __syncthreads();
            }
            if (base + t < N_NODES) off[base + t] = carry + sb[t] - v;
            carry += sb[1023];
            __syncthreads();
        }
        if (t == 0) off[N_NODES] = carry;
        __syncthreads();
    }
}

// ---------------- prep 2: edge fill + zero h + B fragment build, fused by block range ----
#define FILL_BLKS 625
#define ZEROH_BLKS 10016          // M_PAD*HID/256
#define ZRE (NKS*2*16*32)         // 13312
#define CE  (NKS*2*8*32)          // 6656
#define BFRAG_BLKS 78             // ceil(19968/256)

__device__ __forceinline__ float wval(const float* W, int c, int j) {
    if (c >= 195) return 0.f;
    if (c < 65)  return W[(0*65 + c)*64 + j] + W[(2*65 + c)*64 + j];
    if (c < 130) return W[(1*65 + (c-65))*64 + j];
    return W[(3*65 + (c-130))*64 + j];
}
__device__ __forceinline__ u32 packbf(float a, float b) {
    __nv_bfloat162 t = __floats2bfloat162_rn(a, b);
    return *(u32*)&t;
}
__global__ void fill_misc(const int* __restrict__ ei, const float* __restrict__ ew,
                          const float* __restrict__ Wz, const float* __restrict__ bz,
                          const float* __restrict__ Wr, const float* __restrict__ br,
                          const float* __restrict__ Wh, const float* __restrict__ bh) {
    int blk = blockIdx.x, tid = threadIdx.x;
    if (blk < FILL_BLKS) {
        int e = blk*256 + tid;
        if (e >= N_EDGES) return;
        int r = ei[e], c = ei[N_EDGES + e];
        float w = ew[e];
        float dof = g_deg_out[r];
        float cf = (dof > 0.f) ? w / dof : 0.f;
        int p = g_offF[r] + atomicAdd(&g_cntF[r], 1);
        g_srcF[p] = c; g_wF[p] = cf;
        float din = g_deg_in[c];
        float cb = (din > 0.f) ? w / din : 0.f;
        int q = g_offB[c] + atomicAdd(&g_cntB[c], 1);
        g_srcB[q] = r; g_wB[q] = cb;
    } else if (blk < FILL_BLKS + ZEROH_BLKS) {
        int i = (blk - FILL_BLKS)*256 + tid;
        if (i < M_PAD*HID) g_h[i] = 0.f;
    } else {
        int idx = (blk - FILL_BLKS - ZEROH_BLKS)*256 + tid;
        if (idx < 128) g_bzr[idx] = (idx < 64) ? bz[idx] : br[idx - 64];
        if (idx < 64)  g_bh[idx] = bh[idx];
        if (idx < ZRE + CE) {
            int natot = (idx < ZRE) ? 16 : 8;
            int e = (idx < ZRE) ? idx : idx - ZRE;
            int lane = e & 31;
            int na   = (e >> 5) % natot;
            int split = (e / (32*natot)) & 1;
            int ks    = e / (64*natot);
            int k0 = ks*16 + (lane & 3)*2;
            int n  = na*8 + (lane >> 2);
            float v[4];
            if (idx < ZRE) {
                const float* W = (n < 64) ? Wz : Wr;
                int j = n & 63;
                v[0] = wval(W, k0,   j); v[1] = wval(W, k0+1, j);
                v[2] = wval(W, k0+8, j); v[3] = wval(W, k0+9, j);
            } else {
                v[0] = wval(Wh, k0,   n); v[1] = wval(Wh, k0+1, n);
                v[2] = wval(Wh, k0+8, n); v[3] = wval(Wh, k0+9, n);
            }
            float p[4];
            for (int i2 = 0; i2 < 4; i2++) {
                float hi = __bfloat162float(__float2bfloat16(v[i2]));
                p[i2] = split ? (v[i2] - hi) : hi;
            }
            uint2 frag = make_uint2(packbf(p[0], p[1]), packbf(p[2], p[3]));
            if (idx < ZRE) g_BfZr[e] = frag; else g_BfC[e] = frag;
        }
    }
}

// ---------------- fused per-half-step kernel: agg -> smem U (bf16 hi/lo) -> HMMA -> epilogue ----
__device__ __forceinline__ void mma16816(float* d, const u32* a, const u32* b) {
    asm volatile("mma.sync.aligned.m16n8k16.row.col.f32.bf16.bf16.f32 "
        "{%0,%1,%2,%3}, {%4,%5,%6,%7}, {%8,%9}, {%0,%1,%2,%3};"
        : "+f"(d[0]), "+f"(d[1]), "+f"(d[2]), "+f"(d[3])
        : "r"(a[0]), "r"(a[1]), "r"(a[2]), "r"(a[3]), "r"(b[0]), "r"(b[1]));
}
__device__ __forceinline__ void ldmx4(u32* r, u32 addr) {
    asm volatile("ldmatrix.sync.aligned.m8n8.x4.shared.b16 {%0,%1,%2,%3}, [%4];"
        : "=r"(r[0]), "=r"(r[1]), "=r"(r[2]), "=r"(r[3]) : "r"(addr));
}
__device__ __forceinline__ float sigf(float v) { return 1.f / (1.f + __expf(-v)); }

// U channels: [0]=x, [1..64]=h|rh, [65]=aggF_x, [66..129]=aggF_h,
//             [130]=aggB_x, [131..194]=aggB_h, [195..207]=0
template<int NOUT>
__global__ void __launch_bounds__(512) fused_step(const float* __restrict__ x_dis, int t) {
    constexpr int NATOT = NOUT / 8;
    constexpr int NA    = NOUT / 32;
    constexpr int WCOL  = NOUT / 4;

    extern __shared__ __nv_bfloat16 sU[];          // [2][128][208]
    __nv_bfloat16* sUhi = sU;
    __nv_bfloat16* sUlo = sU + 128*KDIM;

    const float* __restrict__ hsrc = (NOUT == 128) ? g_h : g_rh;
    int tid = threadIdx.x;
    int node0 = blockIdx.x * 32;

    // zero pad channels 195..207
    for (int i = tid; i < 128*13; i += 512) {
        int rr = i / 13, cc = 195 + i % 13;
        sUhi[rr*KDIM + cc] = __float2bfloat16(0.f);
        sUlo[rr*KDIM + cc] = __float2bfloat16(0.f);
    }

    // ---- aggregation phase: 16 reps x 512 threads = 8192 (node,b,c) triples ----
#pragma unroll 1
    for (int rep = 0; rep < 16; rep++) {
        int tr = rep*512 + tid;
        int c  = tr & 63, b = (tr >> 6) & 3, nl = tr >> 8;
        int n  = node0 + nl;
        int rowl = nl*4 + b;
        float hv = 0.f, xv = 0.f, aF = 0.f, aB = 0.f, aFx = 0.f, aBx = 0.f;
        if (n < N_NODES) {
            int row = n*BATCH + b;
            hv = hsrc[row*HID + c];
            const float* __restrict__ xb = x_dis + (size_t)(b*T_STEPS + t)*N_NODES;
            if (c == 0) xv = xb[n];
            // forward
            {
                int e = g_offF[n], e1 = g_offF[n+1];
                for (; e + 4 <= e1; e += 4) {
                    int s0 = g_srcF[e], s1 = g_srcF[e+1], s2 = g_srcF[e+2], s3 = g_srcF[e+3];
                    float w0 = g_wF[e], w1 = g_wF[e+1], w2 = g_wF[e+2], w3 = g_wF[e+3];
                    aF += w0*hsrc[(s0*BATCH+b)*HID+c] + w1*hsrc[(s1*BATCH+b)*HID+c]
                        + w2*hsrc[(s2*BATCH+b)*HID+c] + w3*hsrc[(s3*BATCH+b)*HID+c];
                    if (c == 0) aFx += w0*xb[s0] + w1*xb[s1] + w2*xb[s2] + w3*xb[s3];
                }
                for (; e < e1; e++) {
                    int s = g_srcF[e]; float w = g_wF[e];
                    aF += w * hsrc[(s*BATCH+b)*HID+c];
                    if (c == 0) aFx += w * xb[s];
                }
            }
            // backward
            {
                int e = g_offB[n], e1 = g_offB[n+1];
                for (; e + 4 <= e1; e += 4) {
                    int s0 = g_srcB[e], s1 = g_srcB[e+1], s2 = g_srcB[e+2], s3 = g_srcB[e+3];
                    float w0 = g_wB[e], w1 = g_wB[e+1], w2 = g_wB[e+2], w3 = g_wB[e+3];
                    aB += w0*hsrc[(s0*BATCH+b)*HID+c] + w1*hsrc[(s1*BATCH+b)*HID+c]
                        + w2*hsrc[(s2*BATCH+b)*HID+c] + w3*hsrc[(s3*BATCH+b)*HID+c];
                    if (c == 0) aBx += w0*xb[s0] + w1*xb[s1] + w2*xb[s2] + w3*xb[s3];
                }
                for (; e < e1; e++) {
                    int s = g_srcB[e]; float w = g_wB[e];
                    aB += w * hsrc[(s*BATCH+b)*HID+c];
                    if (c == 0) aBx += w * xb[s];
                }
            }
        }
        // store bf16 hi/lo splits
        {
            int base = rowl*KDIM;
            __nv_bfloat16 hh = __float2bfloat16(hv);
            sUhi[base + 1 + c] = hh;
            sUlo[base + 1 + c] = __float2bfloat16(hv - __bfloat162float(hh));
            __nv_bfloat16 fh = __float2bfloat16(aF);
            sUhi[base + 66 + c] = fh;
            sUlo[base + 66 + c] = __float2bfloat16(aF - __bfloat162float(fh));
            __nv_bfloat16 bh_ = __float2bfloat16(aB);
            sUhi[base + 131 + c] = bh_;
            sUlo[base + 131 + c] = __float2bfloat16(aB - __bfloat162float(bh_));
            if (c == 0) {
                __nv_bfloat16 xh = __float2bfloat16(xv);
                sUhi[base] = xh;
                sUlo[base] = __float2bfloat16(xv - __bfloat162float(xh));
                __nv_bfloat16 fx = __float2bfloat16(aFx);
                sUhi[base + 65] = fx;
                sUlo[base + 65] = __float2bfloat16(aFx - __bfloat162float(fx));
                __nv_bfloat16 bx = __float2bfloat16(aBx);
                sUhi[base + 130] = bx;
                sUlo[base + 130] = __float2bfloat16(aBx - __bfloat162float(bx));
            }
        }
    }
    __syncthreads();

    // ---- GEMM phase: 16 warps = 4m x 4n ----
    int wid = tid >> 5, lane = tid & 31;
    int wm = wid & 3, wn = wid >> 2;
    const uint2* __restrict__ Bf = (NOUT == 128) ? g_BfZr : g_BfC;

    u32 uhiB = smem_u32(sUhi);
    u32 uloB = smem_u32(sUlo);
    int rloc = wm*32 + (lane & 15);
    u32 csel = (u32)(lane >> 4) * 16;

    float acc[2][NA][4];
#pragma unroll
    for (int ma = 0; ma < 2; ma++)
#pragma unroll
        for (int j = 0; j < NA; j++)
#pragma unroll
            for (int q = 0; q < 4; q++) acc[ma][j][q] = 0.f;

#pragma unroll 1
    for (int ks = 0; ks < NKS; ks++) {
        u32 kb = (u32)ks * 32;
        u32 ah[2][4], al[2][4];
#pragma unroll
        for (int ma = 0; ma < 2; ma++) {
            u32 off = (u32)(rloc + ma*16) * (KDIM*2) + kb + csel;
            ldmx4(ah[ma], uhiB + off);
            ldmx4(al[ma], uloB + off);
        }
        uint2 bh[NA], bl[NA];
#pragma unroll
        for (int j = 0; j < NA; j++) {
            int na = wn*NA + j;
            bh[j] = Bf[((ks*2 + 0)*NATOT + na)*32 + lane];
            bl[j] = Bf[((ks*2 + 1)*NATOT + na)*32 + lane];
        }
#pragma unroll
        for (int ma = 0; ma < 2; ma++)
#pragma unroll
            for (int j = 0; j < NA; j++) {
                mma16816(acc[ma][j], ah[ma], (const u32*)&bh[j]);
                mma16816(acc[ma][j], ah[ma], (const u32*)&bl[j]);
                mma16816(acc[ma][j], al[ma], (const u32*)&bh[j]);
            }
    }

    // ---- epilogue ----
    int rbase = blockIdx.x*128 + wm*32 + (lane >> 2);
#pragma unroll
    for (int ma = 0; ma < 2; ma++) {
#pragma unroll
        for (int j = 0; j < NA; j++) {
            int col = wn*WCOL + j*8 + (lane & 3)*2;
#pragma unroll
            for (int half = 0; half < 2; half++) {
                int row = rbase + ma*16 + half*8;
                float d0 = acc[ma][j][half*2], d1 = acc[ma][j][half*2 + 1];
                if (NOUT == 128) {
                    if (col < 64) {
                        float2 zv = make_float2(sigf(d0 + g_bzr[col]), sigf(d1 + g_bzr[col+1]));
                        *(float2*)&g_z[row*HID + col] = zv;
                    } else {
                        int jr = col - 64;
                        float2 hv = *(const float2*)&g_h[row*HID + jr];
                        float2 rv = make_float2(sigf(d0 + g_bzr[col]) * hv.x,
                                                sigf(d1 + g_bzr[col+1]) * hv.y);
                        *(float2*)&g_rh[row*HID + jr] = rv;
                    }
                } else {
                    float c0 = tanhf(d0 + g_bh[col]);
                    float c1 = tanhf(d1 + g_bh[col+1]);
                    float2 zv = *(const float2*)&g_z[row*HID + col];
                    float2 hv = *(const float2*)&g_h[row*HID + col];
                    float2 nh = make_float2(zv.x*hv.x + (1.f - zv.x)*c0,
                                            zv.y*hv.y + (1.f - zv.y)*c1);
                    *(float2*)&g_h[row*HID + col] = nh;
                }
            }
        }
    }
}

// ---------------- readout (node 0 only) ----------------
__global__ void readout_kernel(const float* __restrict__ W1, const float* __restrict__ b1,
                               const float* __restrict__ W2, const float* __restrict__ b2,
                               float* __restrict__ out) {
    int tid = threadIdx.x;
    int b = tid >> 6, j = tid & 63;
    float acc = b1[j];
#pragma unroll
    for (int c = 0; c < HID; c++)
        acc += g_h[b*HID + c] * W1[c*HID + j];
    float v = fmaxf(acc, 0.f) * W2[j];
#pragma unroll
    for (int o = 16; o > 0; o >>= 1) v += __shfl_down_sync(0xffffffff, v, o);
    __shared__ float part[8];
    if ((tid & 31) == 0) part[tid >> 5] = v;
    __syncthreads();
    if (j == 0) out[b] = part[b*2] + part[b*2 + 1] + b2[0];
}

// ---------------- launch ----------------
extern "C" void kernel_launch(void* const* d_in, const int* in_sizes, int n_in,
                              void* d_out, int out_size) {
    const float* x_dis = (const float*)d_in[0];
    const int*   ei    = (const int*)  d_in[1];
    const float* ew    = (const float*)d_in[2];
    const float* W_z   = (const float*)d_in[3];
    const float* b_z   = (const float*)d_in[4];
    const float* W_r   = (const float*)d_in[5];
    const float* b_r   = (const float*)d_in[6];
    const float* W_h   = (const float*)d_in[7];
    const float* b_h   = (const float*)d_in[8];
    const float* W_ro1 = (const float*)d_in[9];
    const float* b_ro1 = (const float*)d_in[10];
    const float* W_ro2 = (const float*)d_in[11];
    const float* b_ro2 = (const float*)d_in[12];
    float* out = (float*)d_out;

    const int PREP_SMEM = 4 * 10240 * 4;            // 160 KB
    const int FUSE_SMEM = 2 * 128 * KDIM * 2;       // 104 KB
    cudaFuncSetAttribute(prep_scan, cudaFuncAttributeMaxDynamicSharedMemorySize, PREP_SMEM);
    cudaFuncSetAttribute(fused_step<128>, cudaFuncAttributeMaxDynamicSharedMemorySize, FUSE_SMEM);
    cudaFuncSetAttribute(fused_step<64>,  cudaFuncAttributeMaxDynamicSharedMemorySize, FUSE_SMEM);

    prep_scan<<<1, 1024, PREP_SMEM>>>(ei, ew);
    fill_misc<<<FILL_BLKS + ZEROH_BLKS + BFRAG_BLKS, 256>>>(ei, ew, W_z, b_z, W_r, b_r, W_h, b_h);

    for (int t = 0; t < T_STEPS; t++) {
        fused_step<128><<<M_PAD/128, 512, FUSE_SMEM>>>(x_dis, t);
        fused_step<64> <<<M_PAD/128, 512, FUSE_SMEM>>>(x_dis, t);
    }
    readout_kernel<<<1, 256>>>(W_ro1, b_ro1, W_ro2, b_ro2, out);
}

// round 7
// speedup vs baseline: 1.5682x; 1.5682x over previous
#include <cuda_runtime.h>
#include <cuda_bf16.h>
#include <stdint.h>
#include <math.h>

#define N_NODES 10000
#define N_EDGES 160000
#define BATCH 4
#define T_STEPS 16
#define HID 64
#define M_PAD  40064             // 626 * 64
#define KDIM 208                 // 13 * 16
#define NKS 13
#define SPITCH 216               // smem A pitch in bf16 (432B: conflict-free ldmatrix)

typedef uint32_t u32;

// ---------------- device scratch ----------------
__device__ float g_h [M_PAD*HID];
__device__ float g_z [M_PAD*HID];
__device__ float g_rh[M_PAD*HID];
__device__ __align__(16) __nv_bfloat16 g_Uhi[(size_t)M_PAD*KDIM];
__device__ __align__(16) __nv_bfloat16 g_Ulo[(size_t)M_PAD*KDIM];
__device__ float g_deg_out[N_NODES], g_deg_in[N_NODES];
__device__ int   g_cntF[N_NODES], g_cntB[N_NODES];
__device__ int   g_offF[N_NODES+1], g_offB[N_NODES+1];
__device__ int   g_srcF[N_EDGES], g_srcB[N_EDGES];
__device__ float g_wF[N_EDGES],  g_wB[N_EDGES];
// Prepacked B fragment tables: [ks][split][natom][lane] -> uint2 (b0,b1 of m16n8k16)
__device__ uint2 g_BfZr[NKS*2*16*32];
__device__ uint2 g_BfC [NKS*2*8*32];
__device__ float g_bzr[128], g_bh[64];

__device__ __forceinline__ u32 smem_u32(const void* p) {
    u32 a;
    asm("{ .reg .u64 t; cvta.to.shared.u64 t, %1; cvt.u32.u64 %0, t; }" : "=r"(a) : "l"(p));
    return a;
}

// ---------------- prep 1: single-block histogram + degree + scan ----------------
__global__ void prep_scan(const int* __restrict__ ei, const float* __restrict__ ew) {
    extern __shared__ int sm[];
    int*   cF = sm;
    int*   cB = sm + 10240;
    float* dF = (float*)(sm + 20480);
    float* dB = (float*)(sm + 30720);
    __shared__ int sb[1024];
    int t = threadIdx.x;

    for (int i = t; i < 10240; i += 1024) { cF[i]=0; cB[i]=0; dF[i]=0.f; dB[i]=0.f; }
    __syncthreads();

    for (int e = t; e < N_EDGES; e += 1024) {
        int r = ei[e], c = ei[N_EDGES + e];
        float w = ew[e];
        atomicAdd(&cF[r], 1);
        atomicAdd(&cB[c], 1);
        atomicAdd(&dF[r], w);
        atomicAdd(&dB[c], w);
    }
    __syncthreads();

    for (int i = t; i < N_NODES; i += 1024) {
        g_deg_out[i] = dF[i];
        g_deg_in [i] = dB[i];
        g_cntF[i] = 0;
        g_cntB[i] = 0;
    }

    for (int pass = 0; pass < 2; pass++) {
        const int* cnt = pass == 0 ? cF : cB;
        int*       off = pass == 0 ? g_offF : g_offB;
        int carry = 0;
        for (int base = 0; base < N_NODES; base += 1024) {
            int v = (base + t < N_NODES) ? cnt[base + t] : 0;
            sb[t] = v; __syncthreads();
            for (int o = 1; o < 1024; o <<= 1) {
                int y = (t >= o) ? sb[t - o] : 0;
                __syncthreads();
                sb[t] += y;
                __syncthreads();
            }
            if (base + t < N_NODES) off[base + t] = carry + sb[t] - v;
            carry += sb[1023];
            __syncthreads();
        }
        if (t == 0) off[N_NODES] = carry;
        __syncthreads();
    }
}

// ---------------- prep 2: edge fill + zero h + B fragment build ----------------
#define FILL_BLKS 625
#define ZEROH_BLKS 10016          // M_PAD*HID/256
#define ZRE (NKS*2*16*32)         // 13312
#define CE  (NKS*2*8*32)          // 6656
#define BFRAG_BLKS 78

__device__ __forceinline__ float wval(const float* W, int c, int j) {
    if (c >= 195) return 0.f;
    if (c < 65)  return W[(0*65 + c)*64 + j] + W[(2*65 + c)*64 + j];
    if (c < 130) return W[(1*65 + (c-65))*64 + j];
    return W[(3*65 + (c-130))*64 + j];
}
__device__ __forceinline__ u32 packbf(float a, float b) {
    __nv_bfloat162 t = __floats2bfloat162_rn(a, b);
    return *(u32*)&t;
}
__global__ void fill_misc(const int* __restrict__ ei, const float* __restrict__ ew,
                          const float* __restrict__ Wz, const float* __restrict__ bz,
                          const float* __restrict__ Wr, const float* __restrict__ br,
                          const float* __restrict__ Wh, const float* __restrict__ bh) {
    int blk = blockIdx.x, tid = threadIdx.x;
    if (blk < FILL_BLKS) {
        int e = blk*256 + tid;
        if (e >= N_EDGES) return;
        int r = ei[e], c = ei[N_EDGES + e];
        float w = ew[e];
        float dof = g_deg_out[r];
        float cf = (dof > 0.f) ? w / dof : 0.f;
        int p = g_offF[r] + atomicAdd(&g_cntF[r], 1);
        g_srcF[p] = c; g_wF[p] = cf;
        float din = g_deg_in[c];
        float cb = (din > 0.f) ? w / din : 0.f;
        int q = g_offB[c] + atomicAdd(&g_cntB[c], 1);
        g_srcB[q] = r; g_wB[q] = cb;
    } else if (blk < FILL_BLKS + ZEROH_BLKS) {
        int i = (blk - FILL_BLKS)*256 + tid;
        if (i < M_PAD*HID) g_h[i] = 0.f;
    } else {
        int idx = (blk - FILL_BLKS - ZEROH_BLKS)*256 + tid;
        if (idx < 128) g_bzr[idx] = (idx < 64) ? bz[idx] : br[idx - 64];
        if (idx < 64)  g_bh[idx] = bh[idx];
        if (idx < ZRE + CE) {
            int natot = (idx < ZRE) ? 16 : 8;
            int e = (idx < ZRE) ? idx : idx - ZRE;
            int lane = e & 31;
            int na   = (e >> 5) % natot;
            int split = (e / (32*natot)) & 1;
            int ks    = e / (64*natot);
            int k0 = ks*16 + (lane & 3)*2;
            int n  = na*8 + (lane >> 2);
            float v[4];
            if (idx < ZRE) {
                const float* W = (n < 64) ? Wz : Wr;
                int j = n & 63;
                v[0] = wval(W, k0,   j); v[1] = wval(W, k0+1, j);
                v[2] = wval(W, k0+8, j); v[3] = wval(W, k0+9, j);
            } else {
                v[0] = wval(Wh, k0,   n); v[1] = wval(Wh, k0+1, n);
                v[2] = wval(Wh, k0+8, n); v[3] = wval(Wh, k0+9, n);
            }
            float p[4];
            for (int i2 = 0; i2 < 4; i2++) {
                float hi = __bfloat162float(__float2bfloat16(v[i2]));
                p[i2] = split ? (v[i2] - hi) : hi;
            }
            uint2 frag = make_uint2(packbf(p[0], p[1]), packbf(p[2], p[3]));
            if (idx < ZRE) g_BfZr[e] = frag; else g_BfC[e] = frag;
        }
    }
}

// ---------------- aggregation (block per node, 256 threads): U rows as bf16 hi/lo ----------
__device__ __forceinline__ void storeSplit(size_t idx, float v) {
    __nv_bfloat16 hi = __float2bfloat16(v);
    g_Uhi[idx] = hi;
    g_Ulo[idx] = __float2bfloat16(v - __bfloat162float(hi));
}
__global__ void agg_kernel(const float* __restrict__ x_dis, int t, int full) {
    const float* __restrict__ hsrc = full ? g_h : g_rh;
    int n   = blockIdx.x;
    int tid = threadIdx.x;
    int b = tid >> 6, c = tid & 63;
    int row = n*BATCH + b;
    size_t ub = (size_t)row * KDIM;
    const float* __restrict__ xb = x_dis + (size_t)(b*T_STEPS + t)*N_NODES;

    storeSplit(ub + 1 + c, hsrc[row*HID + c]);
    if (full && c == 0) storeSplit(ub, xb[n]);

    for (int dir = 0; dir < 2; dir++) {
        const int*   off = dir == 0 ? g_offF : g_offB;
        const int*   src = dir == 0 ? g_srcF : g_srcB;
        const float* ww  = dir == 0 ? g_wF   : g_wB;
        int e0 = off[n], e1 = off[n + 1];
        float accH = 0.f, accX = 0.f;
        int e = e0;
        for (; e + 4 <= e1; e += 4) {
            int s0 = src[e], s1 = src[e+1], s2 = src[e+2], s3 = src[e+3];
            float w0 = ww[e], w1 = ww[e+1], w2 = ww[e+2], w3 = ww[e+3];
            accH += w0*hsrc[(s0*BATCH+b)*HID+c] + w1*hsrc[(s1*BATCH+b)*HID+c]
                  + w2*hsrc[(s2*BATCH+b)*HID+c] + w3*hsrc[(s3*BATCH+b)*HID+c];
            if (full && c == 0)
                accX += w0*xb[s0] + w1*xb[s1] + w2*xb[s2] + w3*xb[s3];
        }
        for (; e < e1; e++) {
            int s = src[e]; float w = ww[e];
            accH += w * hsrc[(s*BATCH+b)*HID+c];
            if (full && c == 0) accX += w * xb[s];
        }
        int chbase = dir == 0 ? 65 : 130;
        storeSplit(ub + chbase + 1 + c, accH);
        if (full && c == 0) storeSplit(ub + chbase, accX);
    }
}

// ---------------- HMMA GEMM, smem-staged A + ldmatrix ----------------
__device__ __forceinline__ void mma16816(float* d, const u32* a, const u32* b) {
    asm volatile("mma.sync.aligned.m16n8k16.row.col.f32.bf16.bf16.f32 "
        "{%0,%1,%2,%3}, {%4,%5,%6,%7}, {%8,%9}, {%0,%1,%2,%3};"
        : "+f"(d[0]), "+f"(d[1]), "+f"(d[2]), "+f"(d[3])
        : "r"(a[0]), "r"(a[1]), "r"(a[2]), "r"(a[3]), "r"(b[0]), "r"(b[1]));
}
__device__ __forceinline__ void ldmx4(u32* r, u32 addr) {
    asm volatile("ldmatrix.sync.aligned.m8n8.x4.shared.b16 {%0,%1,%2,%3}, [%4];"
        : "=r"(r[0]), "=r"(r[1]), "=r"(r[2]), "=r"(r[3]) : "r"(addr));
}
__device__ __forceinline__ float sigf(float v) { return 1.f / (1.f + __expf(-v)); }

// BM=64, 256 threads = 8 warps = 2m x 4n. Warp tile 32 x (NOUT/4).
template<int NOUT>
__global__ void __launch_bounds__(256) gemm_kernel() {
    constexpr int NATOT = NOUT / 8;
    constexpr int NA    = NOUT / 32;          // natoms per warp (4 for 128, 2 for 64)
    constexpr int WCOL  = NOUT / 4;

    extern __shared__ __nv_bfloat16 sA[];     // [2][64][SPITCH]
    int tid = threadIdx.x;
    int rowBase = blockIdx.x * 64;

    // stage A (hi, lo): 64 rows x 208 cols, coalesced uint4, 13 per thread
#pragma unroll
    for (int q = 0; q < 13; q++) {
        int idx = tid + q*256;                // 0..3327
        int split = idx >= 1664;
        int rem = split ? idx - 1664 : idx;
        int r = rem / 26, c8 = rem % 26;
        const __nv_bfloat16* src = split ? g_Ulo : g_Uhi;
        uint4 v = *(const uint4*)(src + (size_t)(rowBase + r)*KDIM + c8*8);
        *(uint4*)(sA + (size_t)split*64*SPITCH + r*SPITCH + c8*8) = v;
    }
    __syncthreads();

    int wid = tid >> 5, lane = tid & 31;
    int wm = wid & 1, wn = wid >> 1;          // 2m x 4n
    const uint2* __restrict__ Bf = (NOUT == 128) ? g_BfZr : g_BfC;

    u32 aBase = smem_u32(sA);
    int rloc = wm*32 + (lane & 15);
    u32 csel = (u32)(lane >> 4) * 16;

    float acc[2][NA][4];
#pragma unroll
    for (int ma = 0; ma < 2; ma++)
#pragma unroll
        for (int j = 0; j < NA; j++)
#pragma unroll
            for (int q = 0; q < 4; q++) acc[ma][j][q] = 0.f;

#pragma unroll 1
    for (int ks = 0; ks < NKS; ks++) {
        u32 kb = (u32)ks * 32;
        u32 ah[2][4], al[2][4];
#pragma unroll
        for (int ma = 0; ma < 2; ma++) {
            u32 off = (u32)(rloc + ma*16) * (SPITCH*2) + kb + csel;
            ldmx4(ah[ma], aBase + off);
            ldmx4(al[ma], aBase + (u32)(64*SPITCH*2) + off);
        }
        uint2 bh[NA], bl[NA];
#pragma unroll
        for (int j = 0; j < NA; j++) {
            int na = wn*NA + j;
            bh[j] = Bf[((ks*2 + 0)*NATOT + na)*32 + lane];
            bl[j] = Bf[((ks*2 + 1)*NATOT + na)*32 + lane];
        }
#pragma unroll
        for (int ma = 0; ma < 2; ma++)
#pragma unroll
            for (int j = 0; j < NA; j++) {
                mma16816(acc[ma][j], ah[ma], (const u32*)&bh[j]);
                mma16816(acc[ma][j], ah[ma], (const u32*)&bl[j]);
                mma16816(acc[ma][j], al[ma], (const u32*)&bh[j]);
            }
    }

    // epilogue
    int rbase = rowBase + wm*32 + (lane >> 2);
#pragma unroll
    for (int ma = 0; ma < 2; ma++) {
#pragma unroll
        for (int j = 0; j < NA; j++) {
            int col = wn*WCOL + j*8 + (lane & 3)*2;
#pragma unroll
            for (int half = 0; half < 2; half++) {
                int row = rbase + ma*16 + half*8;
                float d0 = acc[ma][j][half*2], d1 = acc[ma][j][half*2 + 1];
                if (NOUT == 128) {
                    if (col < 64) {
                        float2 zv = make_float2(sigf(d0 + g_bzr[col]), sigf(d1 + g_bzr[col+1]));
                        *(float2*)&g_z[row*HID + col] = zv;
                    } else {
                        int jr = col - 64;
                        float2 hv = *(const float2*)&g_h[row*HID + jr];
                        float2 rv = make_float2(sigf(d0 + g_bzr[col]) * hv.x,
                                                sigf(d1 + g_bzr[col+1]) * hv.y);
                        *(float2*)&g_rh[row*HID + jr] = rv;
                    }
                } else {
                    float c0 = tanhf(d0 + g_bh[col]);
                    float c1 = tanhf(d1 + g_bh[col+1]);
                    float2 zv = *(const float2*)&g_z[row*HID + col];
                    float2 hv = *(const float2*)&g_h[row*HID + col];
                    float2 nh = make_float2(zv.x*hv.x + (1.f - zv.x)*c0,
                                            zv.y*hv.y + (1.f - zv.y)*c1);
                    *(float2*)&g_h[row*HID + col] = nh;
                }
            }
        }
    }
}

// ---------------- readout (node 0 only) ----------------
__global__ void readout_kernel(const float* __restrict__ W1, const float* __restrict__ b1,
                               const float* __restrict__ W2, const float* __restrict__ b2,
                               float* __restrict__ out) {
    int tid = threadIdx.x;
    int b = tid >> 6, j = tid & 63;
    float acc = b1[j];
#pragma unroll
    for (int c = 0; c < HID; c++)
        acc += g_h[b*HID + c] * W1[c*HID + j];
    float v = fmaxf(acc, 0.f) * W2[j];
#pragma unroll
    for (int o = 16; o > 0; o >>= 1) v += __shfl_down_sync(0xffffffff, v, o);
    __shared__ float part[8];
    if ((tid & 31) == 0) part[tid >> 5] = v;
    __syncthreads();
    if (j == 0) out[b] = part[b*2] + part[b*2 + 1] + b2[0];
}

// ---------------- launch ----------------
extern "C" void kernel_launch(void* const* d_in, const int* in_sizes, int n_in,
                              void* d_out, int out_size) {
    const float* x_dis = (const float*)d_in[0];
    const int*   ei    = (const int*)  d_in[1];
    const float* ew    = (const float*)d_in[2];
    const float* W_z   = (const float*)d_in[3];
    const float* b_z   = (const float*)d_in[4];
    const float* W_r   = (const float*)d_in[5];
    const float* b_r   = (const float*)d_in[6];
    const float* W_h   = (const float*)d_in[7];
    const float* b_h   = (const float*)d_in[8];
    const float* W_ro1 = (const float*)d_in[9];
    const float* b_ro1 = (const float*)d_in[10];
    const float* W_ro2 = (const float*)d_in[11];
    const float* b_ro2 = (const float*)d_in[12];
    float* out = (float*)d_out;

    const int PREP_SMEM = 4 * 10240 * 4;                 // 160 KB
    const int GEMM_SMEM = 2 * 64 * SPITCH * 2;           // 55296 B
    cudaFuncSetAttribute(prep_scan, cudaFuncAttributeMaxDynamicSharedMemorySize, PREP_SMEM);
    cudaFuncSetAttribute(gemm_kernel<128>, cudaFuncAttributeMaxDynamicSharedMemorySize, GEMM_SMEM);
    cudaFuncSetAttribute(gemm_kernel<64>,  cudaFuncAttributeMaxDynamicSharedMemorySize, GEMM_SMEM);

    prep_scan<<<1, 1024, PREP_SMEM>>>(ei, ew);
    fill_misc<<<FILL_BLKS + ZEROH_BLKS + BFRAG_BLKS, 256>>>(ei, ew, W_z, b_z, W_r, b_r, W_h, b_h);

    for (int t = 0; t < T_STEPS; t++) {
        agg_kernel<<<N_NODES, 256>>>(x_dis, t, 1);
        gemm_kernel<128><<<M_PAD/64, 256, GEMM_SMEM>>>();
        agg_kernel<<<N_NODES, 256>>>(x_dis, t, 0);
        gemm_kernel<64><<<M_PAD/64, 256, GEMM_SMEM>>>();
    }
    readout_kernel<<<1, 256>>>(W_ro1, b_ro1, W_ro2, b_ro2, out);
}

// round 9
// speedup vs baseline: 1.9508x; 1.2440x over previous
#include <cuda_runtime.h>
#include <cuda_bf16.h>
#include <cuda_fp16.h>
#include <stdint.h>
#include <math.h>

#define N_NODES 10000
#define N_EDGES 160000
#define BATCH 4
#define T_STEPS 16
#define HID 64
#define M_PAD  40064             // 626 * 64
#define KDIM 208                 // 13 * 16
#define NKS 13
#define SPITCH 216               // smem A pitch in bf16 (432B: conflict-free ldmatrix)

typedef uint32_t u32;

// ---------------- device scratch ----------------
__device__ float g_h [M_PAD*HID];
__device__ float g_z [M_PAD*HID];
__device__ float g_rh[M_PAD*HID];
__device__ __align__(16) __half g_hb [M_PAD*HID];   // fp16 mirror of h (gathers)
__device__ __align__(16) __half g_rhb[M_PAD*HID];   // fp16 mirror of rh (gathers)
__device__ __align__(16) __nv_bfloat16 g_Uhi[(size_t)M_PAD*KDIM];
__device__ __align__(16) __nv_bfloat16 g_Ulo[(size_t)M_PAD*KDIM];
__device__ float g_deg_out[N_NODES], g_deg_in[N_NODES];
__device__ int   g_cntF[N_NODES], g_cntB[N_NODES];
__device__ int   g_offF[N_NODES+1], g_offB[N_NODES+1];
__device__ int   g_srcF[N_EDGES], g_srcB[N_EDGES];
__device__ float g_wF[N_EDGES],  g_wB[N_EDGES];
// Prepacked B fragment tables: [ks][split][natom][lane] -> uint2 (b0,b1 of m16n8k16)
__device__ uint2 g_BfZr[NKS*2*16*32];
__device__ uint2 g_BfC [NKS*2*8*32];
__device__ float g_bzr[128], g_bh[64];

__device__ __forceinline__ u32 smem_u32(const void* p) {
    u32 a;
    asm("{ .reg .u64 t; cvta.to.shared.u64 t, %1; cvt.u32.u64 %0, t; }" : "=r"(a) : "l"(p));
    return a;
}

// ---------------- prep 1: single-block histogram + degree + scan ----------------
__global__ void prep_scan(const int* __restrict__ ei, const float* __restrict__ ew) {
    extern __shared__ int sm[];
    int*   cF = sm;
    int*   cB = sm + 10240;
    float* dF = (float*)(sm + 20480);
    float* dB = (float*)(sm + 30720);
    __shared__ int sb[1024];
    int t = threadIdx.x;

    for (int i = t; i < 10240; i += 1024) { cF[i]=0; cB[i]=0; dF[i]=0.f; dB[i]=0.f; }
    __syncthreads();

    for (int e = t; e < N_EDGES; e += 1024) {
        int r = ei[e], c = ei[N_EDGES + e];
        float w = ew[e];
        atomicAdd(&cF[r], 1);
        atomicAdd(&cB[c], 1);
        atomicAdd(&dF[r], w);
        atomicAdd(&dB[c], w);
    }
    __syncthreads();

    for (int i = t; i < N_NODES; i += 1024) {
        g_deg_out[i] = dF[i];
        g_deg_in [i] = dB[i];
        g_cntF[i] = 0;
        g_cntB[i] = 0;
    }

    for (int pass = 0; pass < 2; pass++) {
        const int* cnt = pass == 0 ? cF : cB;
        int*       off = pass == 0 ? g_offF : g_offB;
        int carry = 0;
        for (int base = 0; base < N_NODES; base += 1024) {
            int v = (base + t < N_NODES) ? cnt[base + t] : 0;
            sb[t] = v; __syncthreads();
            for (int o = 1; o < 1024; o <<= 1) {
                int y = (t >= o) ? sb[t - o] : 0;
                __syncthreads();
                sb[t] += y;
                __syncthreads();
            }
            if (base + t < N_NODES) off[base + t] = carry + sb[t] - v;
            carry += sb[1023];
            __syncthreads();
        }
        if (t == 0) off[N_NODES] = carry;
        __syncthreads();
    }
}

// ---------------- prep 2: edge fill + zero h + B fragment build ----------------
#define FILL_BLKS 625
#define ZEROH_BLKS 10016          // M_PAD*HID/256
#define ZRE (NKS*2*16*32)         // 13312
#define CE  (NKS*2*8*32)          // 6656
#define BFRAG_BLKS 78

__device__ __forceinline__ float wval(const float* W, int c, int j) {
    if (c >= 195) return 0.f;
    if (c < 65)  return W[(0*65 + c)*64 + j] + W[(2*65 + c)*64 + j];
    if (c < 130) return W[(1*65 + (c-65))*64 + j];
    return W[(3*65 + (c-130))*64 + j];
}
__device__ __forceinline__ u32 packbf(float a, float b) {
    __nv_bfloat162 t = __floats2bfloat162_rn(a, b);
    return *(u32*)&t;
}
__global__ void fill_misc(const int* __restrict__ ei, const float* __restrict__ ew,
                          const float* __restrict__ Wz, const float* __restrict__ bz,
                          const float* __restrict__ Wr, const float* __restrict__ br,
                          const float* __restrict__ Wh, const float* __restrict__ bh) {
    int blk = blockIdx.x, tid = threadIdx.x;
    if (blk < FILL_BLKS) {
        int e = blk*256 + tid;
        if (e >= N_EDGES) return;
        int r = ei[e], c = ei[N_EDGES + e];
        float w = ew[e];
        float dof = g_deg_out[r];
        float cf = (dof > 0.f) ? w / dof : 0.f;
        int p = g_offF[r] + atomicAdd(&g_cntF[r], 1);
        g_srcF[p] = c; g_wF[p] = cf;
        float din = g_deg_in[c];
        float cb = (din > 0.f) ? w / din : 0.f;
        int q = g_offB[c] + atomicAdd(&g_cntB[c], 1);
        g_srcB[q] = r; g_wB[q] = cb;
    } else if (blk < FILL_BLKS + ZEROH_BLKS) {
        int i = (blk - FILL_BLKS)*256 + tid;
        if (i < M_PAD*HID) { g_h[i] = 0.f; g_hb[i] = __float2half(0.f); }
    } else {
        int idx = (blk - FILL_BLKS - ZEROH_BLKS)*256 + tid;
        if (idx < 128) g_bzr[idx] = (idx < 64) ? bz[idx] : br[idx - 64];
        if (idx < 64)  g_bh[idx] = bh[idx];
        if (idx < ZRE + CE) {
            int natot = (idx < ZRE) ? 16 : 8;
            int e = (idx < ZRE) ? idx : idx - ZRE;
            int lane = e & 31;
            int na   = (e >> 5) % natot;
            int split = (e / (32*natot)) & 1;
            int ks    = e / (64*natot);
            int k0 = ks*16 + (lane & 3)*2;
            int n  = na*8 + (lane >> 2);
            float v[4];
            if (idx < ZRE) {
                const float* W = (n < 64) ? Wz : Wr;
                int j = n & 63;
                v[0] = wval(W, k0,   j); v[1] = wval(W, k0+1, j);
                v[2] = wval(W, k0+8, j); v[3] = wval(W, k0+9, j);
            } else {
                v[0] = wval(Wh, k0,   n); v[1] = wval(Wh, k0+1, n);
                v[2] = wval(Wh, k0+8, n); v[3] = wval(Wh, k0+9, n);
            }
            float p[4];
            for (int i2 = 0; i2 < 4; i2++) {
                float hi = __bfloat162float(__float2bfloat16(v[i2]));
                p[i2] = split ? (v[i2] - hi) : hi;
            }
            uint2 frag = make_uint2(packbf(p[0], p[1]), packbf(p[2], p[3]));
            if (idx < ZRE) g_BfZr[e] = frag; else g_BfC[e] = frag;
        }
    }
}

// ---------------- aggregation: 2 nodes/block, fp16x2 gathers, fp32 accumulate ----------
__device__ __forceinline__ void storeSplit(size_t idx, float v) {
    __nv_bfloat16 hi = __float2bfloat16(v);
    g_Uhi[idx] = hi;
    g_Ulo[idx] = __float2bfloat16(v - __bfloat162float(hi));
}
__global__ void __launch_bounds__(256) agg_kernel(const float* __restrict__ x_dis, int t, int full) {
    const float* __restrict__ hsrcF = full ? g_h : g_rh;    // exact direct channels
    const __half* __restrict__ hb = full ? g_hb : g_rhb;    // gather source (fp16)
    int tid = threadIdx.x;
    int nl = tid >> 7, b = (tid >> 5) & 3, cp = tid & 31;
    int c  = cp * 2;
    int n  = blockIdx.x*2 + nl;
    int row = n*BATCH + b;
    size_t ub = (size_t)row * KDIM;
    const float* __restrict__ xb = x_dis + (size_t)(b*T_STEPS + t)*N_NODES;

    // direct channels (exact fp32)
    storeSplit(ub + 1 + c,     hsrcF[row*HID + c]);
    storeSplit(ub + 1 + c + 1, hsrcF[row*HID + c + 1]);
    if (full && cp == 0) storeSplit(ub, xb[n]);

    for (int dir = 0; dir < 2; dir++) {
        const int*   off = dir == 0 ? g_offF : g_offB;
        const int*   src = dir == 0 ? g_srcF : g_srcB;
        const float* ww  = dir == 0 ? g_wF   : g_wB;
        int e0 = off[n], e1 = off[n + 1];
        float a0 = 0.f, a1 = 0.f, ax = 0.f;
        int e = e0;
        for (; e + 4 <= e1; e += 4) {
            int s0 = src[e], s1 = src[e+1], s2 = src[e+2], s3 = src[e+3];
            float w0 = ww[e], w1 = ww[e+1], w2 = ww[e+2], w3 = ww[e+3];
            __half2 v0 = *(const __half2*)&hb[(s0*BATCH+b)*HID + c];
            __half2 v1 = *(const __half2*)&hb[(s1*BATCH+b)*HID + c];
            __half2 v2 = *(const __half2*)&hb[(s2*BATCH+b)*HID + c];
            __half2 v3 = *(const __half2*)&hb[(s3*BATCH+b)*HID + c];
            a0 += w0*__low2float(v0)  + w1*__low2float(v1)
                + w2*__low2float(v2)  + w3*__low2float(v3);
            a1 += w0*__high2float(v0) + w1*__high2float(v1)
                + w2*__high2float(v2) + w3*__high2float(v3);
            if (full && cp == 0)
                ax += w0*xb[s0] + w1*xb[s1] + w2*xb[s2] + w3*xb[s3];
        }
        for (; e < e1; e++) {
            int s = src[e]; float w = ww[e];
            __half2 v = *(const __half2*)&hb[(s*BATCH+b)*HID + c];
            a0 += w*__low2float(v);
            a1 += w*__high2float(v);
            if (full && cp == 0) ax += w*xb[s];
        }
        int chbase = dir == 0 ? 65 : 130;
        storeSplit(ub + chbase + 1 + c,     a0);
        storeSplit(ub + chbase + 1 + c + 1, a1);
        if (full && cp == 0) storeSplit(ub + chbase, ax);
    }
}

// ---------------- HMMA GEMM, smem-staged A + ldmatrix ----------------
__device__ __forceinline__ void mma16816(float* d, const u32* a, const u32* b) {
    asm volatile("mma.sync.aligned.m16n8k16.row.col.f32.bf16.bf16.f32 "
        "{%0,%1,%2,%3}, {%4,%5,%6,%7}, {%8,%9}, {%0,%1,%2,%3};"
        : "+f"(d[0]), "+f"(d[1]), "+f"(d[2]), "+f"(d[3])
        : "r"(a[0]), "r"(a[1]), "r"(a[2]), "r"(a[3]), "r"(b[0]), "r"(b[1]));
}
__device__ __forceinline__ void ldmx4(u32* r, u32 addr) {
    asm volatile("ldmatrix.sync.aligned.m8n8.x4.shared.b16 {%0,%1,%2,%3}, [%4];"
        : "=r"(r[0]), "=r"(r[1]), "=r"(r[2]), "=r"(r[3]) : "r"(addr));
}
__device__ __forceinline__ float sigf(float v) { return 1.f / (1.f + __expf(-v)); }

// BM=64, 256 threads = 8 warps = 2m x 4n. Warp tile 32 x (NOUT/4).
template<int NOUT>
__global__ void __launch_bounds__(256) gemm_kernel() {
    constexpr int NATOT = NOUT / 8;
    constexpr int NA    = NOUT / 32;
    constexpr int WCOL  = NOUT / 4;

    extern __shared__ __nv_bfloat16 sA[];     // [2][64][SPITCH]
    int tid = threadIdx.x;
    int rowBase = blockIdx.x * 64;

#pragma unroll
    for (int q = 0; q < 13; q++) {
        int idx = tid + q*256;                // 0..3327
        int split = idx >= 1664;
        int rem = split ? idx - 1664 : idx;
        int r = rem / 26, c8 = rem % 26;
        const __nv_bfloat16* src = split ? g_Ulo : g_Uhi;
        uint4 v = *(const uint4*)(src + (size_t)(rowBase + r)*KDIM + c8*8);
        *(uint4*)(sA + (size_t)split*64*SPITCH + r*SPITCH + c8*8) = v;
    }
    __syncthreads();

    int wid = tid >> 5, lane = tid & 31;
    int wm = wid & 1, wn = wid >> 1;
    const uint2* __restrict__ Bf = (NOUT == 128) ? g_BfZr : g_BfC;

    u32 aBase = smem_u32(sA);
    int rloc = wm*32 + (lane & 15);
    u32 csel = (u32)(lane >> 4) * 16;

    float acc[2][NA][4];
#pragma unroll
    for (int ma = 0; ma < 2; ma++)
#pragma unroll
        for (int j = 0; j < NA; j++)
#pragma unroll
            for (int q = 0; q < 4; q++) acc[ma][j][q] = 0.f;

#pragma unroll 1
    for (int ks = 0; ks < NKS; ks++) {
        u32 kb = (u32)ks * 32;
        u32 ah[2][4], al[2][4];
#pragma unroll
        for (int ma = 0; ma < 2; ma++) {
            u32 off = (u32)(rloc + ma*16) * (SPITCH*2) + kb + csel;
            ldmx4(ah[ma], aBase + off);
            ldmx4(al[ma], aBase + (u32)(64*SPITCH*2) + off);
        }
        uint2 bh[NA], bl[NA];
#pragma unroll
        for (int j = 0; j < NA; j++) {
            int na = wn*NA + j;
            bh[j] = Bf[((ks*2 + 0)*NATOT + na)*32 + lane];
            bl[j] = Bf[((ks*2 + 1)*NATOT + na)*32 + lane];
        }
#pragma unroll
        for (int ma = 0; ma < 2; ma++)
#pragma unroll
            for (int j = 0; j < NA; j++) {
                mma16816(acc[ma][j], ah[ma], (const u32*)&bh[j]);
                mma16816(acc[ma][j], ah[ma], (const u32*)&bl[j]);
                mma16816(acc[ma][j], al[ma], (const u32*)&bh[j]);
            }
    }

    // epilogue (also maintains fp16 mirrors for the gather passes)
    int rbase = rowBase + wm*32 + (lane >> 2);
#pragma unroll
    for (int ma = 0; ma < 2; ma++) {
#pragma unroll
        for (int j = 0; j < NA; j++) {
            int col = wn*WCOL + j*8 + (lane & 3)*2;
#pragma unroll
            for (int half = 0; half < 2; half++) {
                int row = rbase + ma*16 + half*8;
                float d0 = acc[ma][j][half*2], d1 = acc[ma][j][half*2 + 1];
                if (NOUT == 128) {
                    if (col < 64) {
                        float2 zv = make_float2(sigf(d0 + g_bzr[col]), sigf(d1 + g_bzr[col+1]));
                        *(float2*)&g_z[row*HID + col] = zv;
                    } else {
                        int jr = col - 64;
                        float2 hv = *(const float2*)&g_h[row*HID + jr];
                        float2 rv = make_float2(sigf(d0 + g_bzr[col]) * hv.x,
                                                sigf(d1 + g_bzr[col+1]) * hv.y);
                        *(float2*)&g_rh[row*HID + jr] = rv;
                        *(__half2*)&g_rhb[row*HID + jr] = __floats2half2_rn(rv.x, rv.y);
                    }
                } else {
                    float c0 = tanhf(d0 + g_bh[col]);
                    float c1 = tanhf(d1 + g_bh[col+1]);
                    float2 zv = *(const float2*)&g_z[row*HID + col];
                    float2 hv = *(const float2*)&g_h[row*HID + col];
                    float2 nh = make_float2(zv.x*hv.x + (1.f - zv.x)*c0,
                                            zv.y*hv.y + (1.f - zv.y)*c1);
                    *(float2*)&g_h[row*HID + col] = nh;
                    *(__half2*)&g_hb[row*HID + col] = __floats2half2_rn(nh.x, nh.y);
                }
            }
        }
    }
}

// ---------------- readout (node 0 only) ----------------
__global__ void readout_kernel(const float* __restrict__ W1, const float* __restrict__ b1,
                               const float* __restrict__ W2, const float* __restrict__ b2,
                               float* __restrict__ out) {
    int tid = threadIdx.x;
    int b = tid >> 6, j = tid & 63;
    float acc = b1[j];
#pragma unroll
    for (int c = 0; c < HID; c++)
        acc += g_h[b*HID + c] * W1[c*HID + j];
    float v = fmaxf(acc, 0.f) * W2[j];
#pragma unroll
    for (int o = 16; o > 0; o >>= 1) v += __shfl_down_sync(0xffffffff, v, o);
    __shared__ float part[8];
    if ((tid & 31) == 0) part[tid >> 5] = v;
    __syncthreads();
    if (j == 0) out[b] = part[b*2] + part[b*2 + 1] + b2[0];
}

// ---------------- launch ----------------
extern "C" void kernel_launch(void* const* d_in, const int* in_sizes, int n_in,
                              void* d_out, int out_size) {
    const float* x_dis = (const float*)d_in[0];
    const int*   ei    = (const int*)  d_in[1];
    const float* ew    = (const float*)d_in[2];
    const float* W_z   = (const float*)d_in[3];
    const float* b_z   = (const float*)d_in[4];
    const float* W_r   = (const float*)d_in[5];
    const float* b_r   = (const float*)d_in[6];
    const float* W_h   = (const float*)d_in[7];
    const float* b_h   = (const float*)d_in[8];
    const float* W_ro1 = (const float*)d_in[9];
    const float* b_ro1 = (const float*)d_in[10];
    const float* W_ro2 = (const float*)d_in[11];
    const float* b_ro2 = (const float*)d_in[12];
    float* out = (float*)d_out;

    const int PREP_SMEM = 4 * 10240 * 4;                 // 160 KB
    const int GEMM_SMEM = 2 * 64 * SPITCH * 2;           // 55296 B
    cudaFuncSetAttribute(prep_scan, cudaFuncAttributeMaxDynamicSharedMemorySize, PREP_SMEM);
    cudaFuncSetAttribute(gemm_kernel<128>, cudaFuncAttributeMaxDynamicSharedMemorySize, GEMM_SMEM);
    cudaFuncSetAttribute(gemm_kernel<64>,  cudaFuncAttributeMaxDynamicSharedMemorySize, GEMM_SMEM);

    prep_scan<<<1, 1024, PREP_SMEM>>>(ei, ew);
    fill_misc<<<FILL_BLKS + ZEROH_BLKS + BFRAG_BLKS, 256>>>(ei, ew, W_z, b_z, W_r, b_r, W_h, b_h);

    for (int t = 0; t < T_STEPS; t++) {
        agg_kernel<<<N_NODES/2, 256>>>(x_dis, t, 1);
        gemm_kernel<128><<<M_PAD/64, 256, GEMM_SMEM>>>();
        agg_kernel<<<N_NODES/2, 256>>>(x_dis, t, 0);
        gemm_kernel<64><<<M_PAD/64, 256, GEMM_SMEM>>>();
    }
    readout_kernel<<<1, 256>>>(W_ro1, b_ro1, W_ro2, b_ro2, out);
}

// round 10
// speedup vs baseline: 2.2908x; 1.1743x over previous
#include <cuda_runtime.h>
#include <cuda_fp16.h>
#include <stdint.h>
#include <math.h>

#define N_NODES 10000
#define N_EDGES 160000
#define BATCH 4
#define T_STEPS 16
#define HID 64
#define M_PAD  40064             // 626 * 64
#define KDIM 208                 // 13 * 16
#define NKS 13
#define SPITCH 216               // smem A pitch in halves (432B: conflict-free ldmatrix)

typedef uint32_t u32;

// ---------------- device scratch ----------------
__device__ float g_h [M_PAD*HID];
__device__ float g_z [M_PAD*HID];
__device__ float g_rh[M_PAD*HID];
__device__ __align__(16) __half g_hb [M_PAD*HID];   // fp16 mirror of h (gathers)
__device__ __align__(16) __half g_rhb[M_PAD*HID];   // fp16 mirror of rh (gathers)
__device__ __align__(16) __half g_U  [(size_t)M_PAD*KDIM];   // fp16 activations (GEMM A)
__device__ float g_deg_out[N_NODES], g_deg_in[N_NODES];
__device__ int   g_cntF[N_NODES], g_cntB[N_NODES];
__device__ int   g_offF[N_NODES+1], g_offB[N_NODES+1];
__device__ int   g_srcF[N_EDGES], g_srcB[N_EDGES];
__device__ float g_wF[N_EDGES],  g_wB[N_EDGES];
// Prepacked B fragment tables (fp16 hi/lo): [ks][split][natom][lane] -> uint2
__device__ uint2 g_BfZr[NKS*2*16*32];
__device__ uint2 g_BfC [NKS*2*8*32];
__device__ float g_bzr[128], g_bh[64];

__device__ __forceinline__ u32 smem_u32(const void* p) {
    u32 a;
    asm("{ .reg .u64 t; cvta.to.shared.u64 t, %1; cvt.u32.u64 %0, t; }" : "=r"(a) : "l"(p));
    return a;
}

// ---------------- prep 1: single-block histogram + degree + scan ----------------
__global__ void prep_scan(const int* __restrict__ ei, const float* __restrict__ ew) {
    extern __shared__ int sm[];
    int*   cF = sm;
    int*   cB = sm + 10240;
    float* dF = (float*)(sm + 20480);
    float* dB = (float*)(sm + 30720);
    __shared__ int sb[1024];
    int t = threadIdx.x;

    for (int i = t; i < 10240; i += 1024) { cF[i]=0; cB[i]=0; dF[i]=0.f; dB[i]=0.f; }
    __syncthreads();

    for (int e = t; e < N_EDGES; e += 1024) {
        int r = ei[e], c = ei[N_EDGES + e];
        float w = ew[e];
        atomicAdd(&cF[r], 1);
        atomicAdd(&cB[c], 1);
        atomicAdd(&dF[r], w);
        atomicAdd(&dB[c], w);
    }
    __syncthreads();

    for (int i = t; i < N_NODES; i += 1024) {
        g_deg_out[i] = dF[i];
        g_deg_in [i] = dB[i];
        g_cntF[i] = 0;
        g_cntB[i] = 0;
    }

    for (int pass = 0; pass < 2; pass++) {
        const int* cnt = pass == 0 ? cF : cB;
        int*       off = pass == 0 ? g_offF : g_offB;
        int carry = 0;
        for (int base = 0; base < N_NODES; base += 1024) {
            int v = (base + t < N_NODES) ? cnt[base + t] : 0;
            sb[t] = v; __syncthreads();
            for (int o = 1; o < 1024; o <<= 1) {
                int y = (t >= o) ? sb[t - o] : 0;
                __syncthreads();
                sb[t] += y;
                __syncthreads();
            }
            if (base + t < N_NODES) off[base + t] = carry + sb[t] - v;
            carry += sb[1023];
            __syncthreads();
        }
        if (t == 0) off[N_NODES] = carry;
        __syncthreads();
    }
}

// ---------------- prep 2: edge fill + zero h + B fragment build ----------------
#define FILL_BLKS 625
#define ZEROH_BLKS 10016          // M_PAD*HID/256
#define ZRE (NKS*2*16*32)         // 13312
#define CE  (NKS*2*8*32)          // 6656
#define BFRAG_BLKS 78

__device__ __forceinline__ float wval(const float* W, int c, int j) {
    if (c >= 195) return 0.f;
    if (c < 65)  return W[(0*65 + c)*64 + j] + W[(2*65 + c)*64 + j];
    if (c < 130) return W[(1*65 + (c-65))*64 + j];
    return W[(3*65 + (c-130))*64 + j];
}
__device__ __forceinline__ u32 packh(float a, float b) {
    __half2 t = __floats2half2_rn(a, b);
    return *(u32*)&t;
}
__global__ void fill_misc(const int* __restrict__ ei, const float* __restrict__ ew,
                          const float* __restrict__ Wz, const float* __restrict__ bz,
                          const float* __restrict__ Wr, const float* __restrict__ br,
                          const float* __restrict__ Wh, const float* __restrict__ bh) {
    int blk = blockIdx.x, tid = threadIdx.x;
    if (blk < FILL_BLKS) {
        int e = blk*256 + tid;
        if (e >= N_EDGES) return;
        int r = ei[e], c = ei[N_EDGES + e];
        float w = ew[e];
        float dof = g_deg_out[r];
        float cf = (dof > 0.f) ? w / dof : 0.f;
        int p = g_offF[r] + atomicAdd(&g_cntF[r], 1);
        g_srcF[p] = c; g_wF[p] = cf;
        float din = g_deg_in[c];
        float cb = (din > 0.f) ? w / din : 0.f;
        int q = g_offB[c] + atomicAdd(&g_cntB[c], 1);
        g_srcB[q] = r; g_wB[q] = cb;
    } else if (blk < FILL_BLKS + ZEROH_BLKS) {
        int i = (blk - FILL_BLKS)*256 + tid;
        if (i < M_PAD*HID) { g_h[i] = 0.f; g_hb[i] = __float2half(0.f); }
    } else {
        int idx = (blk - FILL_BLKS - ZEROH_BLKS)*256 + tid;
        if (idx < 128) g_bzr[idx] = (idx < 64) ? bz[idx] : br[idx - 64];
        if (idx < 64)  g_bh[idx] = bh[idx];
        if (idx < ZRE + CE) {
            int natot = (idx < ZRE) ? 16 : 8;
            int e = (idx < ZRE) ? idx : idx - ZRE;
            int lane = e & 31;
            int na   = (e >> 5) % natot;
            int split = (e / (32*natot)) & 1;
            int ks    = e / (64*natot);
            int k0 = ks*16 + (lane & 3)*2;
            int n  = na*8 + (lane >> 2);
            float v[4];
            if (idx < ZRE) {
                const float* W = (n < 64) ? Wz : Wr;
                int j = n & 63;
                v[0] = wval(W, k0,   j); v[1] = wval(W, k0+1, j);
                v[2] = wval(W, k0+8, j); v[3] = wval(W, k0+9, j);
            } else {
                v[0] = wval(Wh, k0,   n); v[1] = wval(Wh, k0+1, n);
                v[2] = wval(Wh, k0+8, n); v[3] = wval(Wh, k0+9, n);
            }
            float p[4];
            for (int i2 = 0; i2 < 4; i2++) {
                float hi = __half2float(__float2half(v[i2]));
                p[i2] = split ? (v[i2] - hi) : hi;
            }
            uint2 frag = make_uint2(packh(p[0], p[1]), packh(p[2], p[3]));
            if (idx < ZRE) g_BfZr[e] = frag; else g_BfC[e] = frag;
        }
    }
}

// ---------------- aggregation: 2 nodes/block, fp16x2 gathers, fp32 accumulate ----------
__global__ void __launch_bounds__(256) agg_kernel(const float* __restrict__ x_dis, int t, int full) {
    const float* __restrict__ hsrcF = full ? g_h : g_rh;    // exact direct channels
    const __half* __restrict__ hb = full ? g_hb : g_rhb;    // gather source (fp16)
    int tid = threadIdx.x;
    int nl = tid >> 7, b = (tid >> 5) & 3, cp = tid & 31;
    int c  = cp * 2;
    int n  = blockIdx.x*2 + nl;
    int row = n*BATCH + b;
    size_t ub = (size_t)row * KDIM;
    const float* __restrict__ xb = x_dis + (size_t)(b*T_STEPS + t)*N_NODES;

    // direct channels
    g_U[ub + 1 + c]     = __float2half(hsrcF[row*HID + c]);
    g_U[ub + 1 + c + 1] = __float2half(hsrcF[row*HID + c + 1]);
    if (full && cp == 0) g_U[ub] = __float2half(xb[n]);

    for (int dir = 0; dir < 2; dir++) {
        const int*   off = dir == 0 ? g_offF : g_offB;
        const int*   src = dir == 0 ? g_srcF : g_srcB;
        const float* ww  = dir == 0 ? g_wF   : g_wB;
        int e0 = off[n], e1 = off[n + 1];
        float a0 = 0.f, a1 = 0.f, ax = 0.f;
        int e = e0;
        for (; e + 4 <= e1; e += 4) {
            int s0 = src[e], s1 = src[e+1], s2 = src[e+2], s3 = src[e+3];
            float w0 = ww[e], w1 = ww[e+1], w2 = ww[e+2], w3 = ww[e+3];
            __half2 v0 = *(const __half2*)&hb[(s0*BATCH+b)*HID + c];
            __half2 v1 = *(const __half2*)&hb[(s1*BATCH+b)*HID + c];
            __half2 v2 = *(const __half2*)&hb[(s2*BATCH+b)*HID + c];
            __half2 v3 = *(const __half2*)&hb[(s3*BATCH+b)*HID + c];
            a0 += w0*__low2float(v0)  + w1*__low2float(v1)
                + w2*__low2float(v2)  + w3*__low2float(v3);
            a1 += w0*__high2float(v0) + w1*__high2float(v1)
                + w2*__high2float(v2) + w3*__high2float(v3);
            if (full && cp == 0)
                ax += w0*xb[s0] + w1*xb[s1] + w2*xb[s2] + w3*xb[s3];
        }
        for (; e < e1; e++) {
            int s = src[e]; float w = ww[e];
            __half2 v = *(const __half2*)&hb[(s*BATCH+b)*HID + c];
            a0 += w*__low2float(v);
            a1 += w*__high2float(v);
            if (full && cp == 0) ax += w*xb[s];
        }
        int chbase = dir == 0 ? 65 : 130;
        g_U[ub + chbase + 1 + c]     = __float2half(a0);
        g_U[ub + chbase + 1 + c + 1] = __float2half(a1);
        if (full && cp == 0) g_U[ub + chbase] = __float2half(ax);
    }
}

// ---------------- HMMA GEMM (fp16 A, fp16 hi/lo B), smem-staged A + ldmatrix ----------
__device__ __forceinline__ void mma16816(float* d, const u32* a, const u32* b) {
    asm volatile("mma.sync.aligned.m16n8k16.row.col.f32.f16.f16.f32 "
        "{%0,%1,%2,%3}, {%4,%5,%6,%7}, {%8,%9}, {%0,%1,%2,%3};"
        : "+f"(d[0]), "+f"(d[1]), "+f"(d[2]), "+f"(d[3])
        : "r"(a[0]), "r"(a[1]), "r"(a[2]), "r"(a[3]), "r"(b[0]), "r"(b[1]));
}
__device__ __forceinline__ void ldmx4(u32* r, u32 addr) {
    asm volatile("ldmatrix.sync.aligned.m8n8.x4.shared.b16 {%0,%1,%2,%3}, [%4];"
        : "=r"(r[0]), "=r"(r[1]), "=r"(r[2]), "=r"(r[3]) : "r"(addr));
}
__device__ __forceinline__ float sigf(float v) { return 1.f / (1.f + __expf(-v)); }

// BM=64, 256 threads = 8 warps = 2m x 4n. Warp tile 32 x (NOUT/4).
template<int NOUT>
__global__ void __launch_bounds__(256) gemm_kernel() {
    constexpr int NATOT = NOUT / 8;
    constexpr int NA    = NOUT / 32;
    constexpr int WCOL  = NOUT / 4;

    extern __shared__ __half sA[];            // [64][SPITCH]
    int tid = threadIdx.x;
    int rowBase = blockIdx.x * 64;

    // stage A: 64 rows x 208 cols fp16 = 1664 uint4, coalesced
#pragma unroll
    for (int q = 0; q < 7; q++) {
        int idx = tid + q*256;
        if (idx < 1664) {
            int r = idx / 26, c8 = idx % 26;
            uint4 v = *(const uint4*)(g_U + (size_t)(rowBase + r)*KDIM + c8*8);
            *(uint4*)(sA + r*SPITCH + c8*8) = v;
        }
    }
    __syncthreads();

    int wid = tid >> 5, lane = tid & 31;
    int wm = wid & 1, wn = wid >> 1;
    const uint2* __restrict__ Bf = (NOUT == 128) ? g_BfZr : g_BfC;

    u32 aBase = smem_u32(sA);
    int rloc = wm*32 + (lane & 15);
    u32 csel = (u32)(lane >> 4) * 16;

    float acc[2][NA][4];
#pragma unroll
    for (int ma = 0; ma < 2; ma++)
#pragma unroll
        for (int j = 0; j < NA; j++)
#pragma unroll
            for (int q = 0; q < 4; q++) acc[ma][j][q] = 0.f;

#pragma unroll 1
    for (int ks = 0; ks < NKS; ks++) {
        u32 kb = (u32)ks * 32;
        u32 a[2][4];
#pragma unroll
        for (int ma = 0; ma < 2; ma++) {
            u32 off = (u32)(rloc + ma*16) * (SPITCH*2) + kb + csel;
            ldmx4(a[ma], aBase + off);
        }
        uint2 bh[NA], bl[NA];
#pragma unroll
        for (int j = 0; j < NA; j++) {
            int na = wn*NA + j;
            bh[j] = Bf[((ks*2 + 0)*NATOT + na)*32 + lane];
            bl[j] = Bf[((ks*2 + 1)*NATOT + na)*32 + lane];
        }
#pragma unroll
        for (int ma = 0; ma < 2; ma++)
#pragma unroll
            for (int j = 0; j < NA; j++) {
                mma16816(acc[ma][j], a[ma], (const u32*)&bh[j]);
                mma16816(acc[ma][j], a[ma], (const u32*)&bl[j]);
            }
    }

    // epilogue (also maintains fp16 mirrors for the gather passes)
    int rbase = rowBase + wm*32 + (lane >> 2);
#pragma unroll
    for (int ma = 0; ma < 2; ma++) {
#pragma unroll
        for (int j = 0; j < NA; j++) {
            int col = wn*WCOL + j*8 + (lane & 3)*2;
#pragma unroll
            for (int half = 0; half < 2; half++) {
                int row = rbase + ma*16 + half*8;
                float d0 = acc[ma][j][half*2], d1 = acc[ma][j][half*2 + 1];
                if (NOUT == 128) {
                    if (col < 64) {
                        float2 zv = make_float2(sigf(d0 + g_bzr[col]), sigf(d1 + g_bzr[col+1]));
                        *(float2*)&g_z[row*HID + col] = zv;
                    } else {
                        int jr = col - 64;
                        float2 hv = *(const float2*)&g_h[row*HID + jr];
                        float2 rv = make_float2(sigf(d0 + g_bzr[col]) * hv.x,
                                                sigf(d1 + g_bzr[col+1]) * hv.y);
                        *(float2*)&g_rh[row*HID + jr] = rv;
                        *(__half2*)&g_rhb[row*HID + jr] = __floats2half2_rn(rv.x, rv.y);
                    }
                } else {
                    float c0 = tanhf(d0 + g_bh[col]);
                    float c1 = tanhf(d1 + g_bh[col+1]);
                    float2 zv = *(const float2*)&g_z[row*HID + col];
                    float2 hv = *(const float2*)&g_h[row*HID + col];
                    float2 nh = make_float2(zv.x*hv.x + (1.f - zv.x)*c0,
                                            zv.y*hv.y + (1.f - zv.y)*c1);
                    *(float2*)&g_h[row*HID + col] = nh;
                    *(__half2*)&g_hb[row*HID + col] = __floats2half2_rn(nh.x, nh.y);
                }
            }
        }
    }
}

// ---------------- readout (node 0 only) ----------------
__global__ void readout_kernel(const float* __restrict__ W1, const float* __restrict__ b1,
                               const float* __restrict__ W2, const float* __restrict__ b2,
                               float* __restrict__ out) {
    int tid = threadIdx.x;
    int b = tid >> 6, j = tid & 63;
    float acc = b1[j];
#pragma unroll
    for (int c = 0; c < HID; c++)
        acc += g_h[b*HID + c] * W1[c*HID + j];
    float v = fmaxf(acc, 0.f) * W2[j];
#pragma unroll
    for (int o = 16; o > 0; o >>= 1) v += __shfl_down_sync(0xffffffff, v, o);
    __shared__ float part[8];
    if ((tid & 31) == 0) part[tid >> 5] = v;
    __syncthreads();
    if (j == 0) out[b] = part[b*2] + part[b*2 + 1] + b2[0];
}

// ---------------- launch ----------------
extern "C" void kernel_launch(void* const* d_in, const int* in_sizes, int n_in,
                              void* d_out, int out_size) {
    const float* x_dis = (const float*)d_in[0];
    const int*   ei    = (const int*)  d_in[1];
    const float* ew    = (const float*)d_in[2];
    const float* W_z   = (const float*)d_in[3];
    const float* b_z   = (const float*)d_in[4];
    const float* W_r   = (const float*)d_in[5];
    const float* b_r   = (const float*)d_in[6];
    const float* W_h   = (const float*)d_in[7];
    const float* b_h   = (const float*)d_in[8];
    const float* W_ro1 = (const float*)d_in[9];
    const float* b_ro1 = (const float*)d_in[10];
    const float* W_ro2 = (const float*)d_in[11];
    const float* b_ro2 = (const float*)d_in[12];
    float* out = (float*)d_out;

    const int PREP_SMEM = 4 * 10240 * 4;                 // 160 KB
    const int GEMM_SMEM = 64 * SPITCH * 2;               // 27648 B
    cudaFuncSetAttribute(prep_scan, cudaFuncAttributeMaxDynamicSharedMemorySize, PREP_SMEM);
    cudaFuncSetAttribute(gemm_kernel<128>, cudaFuncAttributeMaxDynamicSharedMemorySize, GEMM_SMEM);
    cudaFuncSetAttribute(gemm_kernel<64>,  cudaFuncAttributeMaxDynamicSharedMemorySize, GEMM_SMEM);

    prep_scan<<<1, 1024, PREP_SMEM>>>(ei, ew);
    fill_misc<<<FILL_BLKS + ZEROH_BLKS + BFRAG_BLKS, 256>>>(ei, ew, W_z, b_z, W_r, b_r, W_h, b_h);

    for (int t = 0; t < T_STEPS; t++) {
        agg_kernel<<<N_NODES/2, 256>>>(x_dis, t, 1);
        gemm_kernel<128><<<M_PAD/64, 256, GEMM_SMEM>>>();
        agg_kernel<<<N_NODES/2, 256>>>(x_dis, t, 0);
        gemm_kernel<64><<<M_PAD/64, 256, GEMM_SMEM>>>();
    }
    readout_kernel<<<1, 256>>>(W_ro1, b_ro1, W_ro2, b_ro2, out);
}

// round 11
// speedup vs baseline: 2.4923x; 1.0880x over previous
#include <cuda_runtime.h>
#include <cuda_fp16.h>
#include <stdint.h>
#include <math.h>

#define N_NODES 10000
#define N_EDGES 160000
#define BATCH 4
#define T_STEPS 16
#define HID 64
#define M_PAD  40064             // 626 * 64
#define KDIM 208                 // 13 * 16
#define NKS 13
#define SPITCH 216               // smem A pitch in halves (432B: conflict-free ldmatrix)

typedef uint32_t u32;

// ---------------- device scratch ----------------
__device__ float g_h [M_PAD*HID];
__device__ float g_z [M_PAD*HID];
__device__ __align__(16) __half g_hb [M_PAD*HID];   // fp16 mirror of h
__device__ __align__(16) __half g_rhb[M_PAD*HID];   // fp16 rh (only representation)
__device__ __align__(16) __half g_U  [(size_t)M_PAD*KDIM];   // fp16 activations (GEMM A)
__device__ float g_deg_out[N_NODES], g_deg_in[N_NODES];
__device__ int   g_cntF[N_NODES], g_cntB[N_NODES];
__device__ int   g_offF[N_NODES+1], g_offB[N_NODES+1];
__device__ int   g_srcF[N_EDGES], g_srcB[N_EDGES];
__device__ float g_wF[N_EDGES],  g_wB[N_EDGES];
// Prepacked B fragment tables (fp16 hi/lo): [ks][split][natom][lane] -> uint2
__device__ uint2 g_BfZr[NKS*2*16*32];
__device__ uint2 g_BfC [NKS*2*8*32];
__device__ float g_bzr[128], g_bh[64];

__device__ __forceinline__ u32 smem_u32(const void* p) {
    u32 a;
    asm("{ .reg .u64 t; cvta.to.shared.u64 t, %1; cvt.u32.u64 %0, t; }" : "=r"(a) : "l"(p));
    return a;
}

// ---------------- prep 1: single-block histogram + degree + scan ----------------
__global__ void prep_scan(const int* __restrict__ ei, const float* __restrict__ ew) {
    extern __shared__ int sm[];
    int*   cF = sm;
    int*   cB = sm + 10240;
    float* dF = (float*)(sm + 20480);
    float* dB = (float*)(sm + 30720);
    __shared__ int sb[1024];
    int t = threadIdx.x;

    for (int i = t; i < 10240; i += 1024) { cF[i]=0; cB[i]=0; dF[i]=0.f; dB[i]=0.f; }
    __syncthreads();

    for (int e = t; e < N_EDGES; e += 1024) {
        int r = ei[e], c = ei[N_EDGES + e];
        float w = ew[e];
        atomicAdd(&cF[r], 1);
        atomicAdd(&cB[c], 1);
        atomicAdd(&dF[r], w);
        atomicAdd(&dB[c], w);
    }
    __syncthreads();

    for (int i = t; i < N_NODES; i += 1024) {
        g_deg_out[i] = dF[i];
        g_deg_in [i] = dB[i];
        g_cntF[i] = 0;
        g_cntB[i] = 0;
    }

    for (int pass = 0; pass < 2; pass++) {
        const int* cnt = pass == 0 ? cF : cB;
        int*       off = pass == 0 ? g_offF : g_offB;
        int carry = 0;
        for (int base = 0; base < N_NODES; base += 1024) {
            int v = (base + t < N_NODES) ? cnt[base + t] : 0;
            sb[t] = v; __syncthreads();
            for (int o = 1; o < 1024; o <<= 1) {
                int y = (t >= o) ? sb[t - o] : 0;
                __syncthreads();
                sb[t] += y;
                __syncthreads();
            }
            if (base + t < N_NODES) off[base + t] = carry + sb[t] - v;
            carry += sb[1023];
            __syncthreads();
        }
        if (t == 0) off[N_NODES] = carry;
        __syncthreads();
    }
}

// ---------------- prep 2: edge fill + zero h + B fragment build ----------------
#define FILL_BLKS 625
#define ZEROH_BLKS 10016          // M_PAD*HID/256
#define ZRE (NKS*2*16*32)         // 13312
#define CE  (NKS*2*8*32)          // 6656
#define BFRAG_BLKS 78

__device__ __forceinline__ float wval(const float* W, int c, int j) {
    if (c >= 195) return 0.f;
    if (c < 65)  return W[(0*65 + c)*64 + j] + W[(2*65 + c)*64 + j];
    if (c < 130) return W[(1*65 + (c-65))*64 + j];
    return W[(3*65 + (c-130))*64 + j];
}
__device__ __forceinline__ u32 packh(float a, float b) {
    __half2 t = __floats2half2_rn(a, b);
    return *(u32*)&t;
}
__global__ void fill_misc(const int* __restrict__ ei, const float* __restrict__ ew,
                          const float* __restrict__ Wz, const float* __restrict__ bz,
                          const float* __restrict__ Wr, const float* __restrict__ br,
                          const float* __restrict__ Wh, const float* __restrict__ bh) {
    int blk = blockIdx.x, tid = threadIdx.x;
    if (blk < FILL_BLKS) {
        int e = blk*256 + tid;
        if (e >= N_EDGES) return;
        int r = ei[e], c = ei[N_EDGES + e];
        float w = ew[e];
        float dof = g_deg_out[r];
        float cf = (dof > 0.f) ? w / dof : 0.f;
        int p = g_offF[r] + atomicAdd(&g_cntF[r], 1);
        g_srcF[p] = c; g_wF[p] = cf;
        float din = g_deg_in[c];
        float cb = (din > 0.f) ? w / din : 0.f;
        int q = g_offB[c] + atomicAdd(&g_cntB[c], 1);
        g_srcB[q] = r; g_wB[q] = cb;
    } else if (blk < FILL_BLKS + ZEROH_BLKS) {
        int i = (blk - FILL_BLKS)*256 + tid;
        if (i < M_PAD*HID) { g_h[i] = 0.f; g_hb[i] = __float2half(0.f); }
    } else {
        int idx = (blk - FILL_BLKS - ZEROH_BLKS)*256 + tid;
        if (idx < 128) g_bzr[idx] = (idx < 64) ? bz[idx] : br[idx - 64];
        if (idx < 64)  g_bh[idx] = bh[idx];
        if (idx < ZRE + CE) {
            int natot = (idx < ZRE) ? 16 : 8;
            int e = (idx < ZRE) ? idx : idx - ZRE;
            int lane = e & 31;
            int na   = (e >> 5) % natot;
            int split = (e / (32*natot)) & 1;
            int ks    = e / (64*natot);
            int k0 = ks*16 + (lane & 3)*2;
            int n  = na*8 + (lane >> 2);
            float v[4];
            if (idx < ZRE) {
                const float* W = (n < 64) ? Wz : Wr;
                int j = n & 63;
                v[0] = wval(W, k0,   j); v[1] = wval(W, k0+1, j);
                v[2] = wval(W, k0+8, j); v[3] = wval(W, k0+9, j);
            } else {
                v[0] = wval(Wh, k0,   n); v[1] = wval(Wh, k0+1, n);
                v[2] = wval(Wh, k0+8, n); v[3] = wval(Wh, k0+9, n);
            }
            float p[4];
            for (int i2 = 0; i2 < 4; i2++) {
                float hi = __half2float(__float2half(v[i2]));
                p[i2] = split ? (v[i2] - hi) : hi;
            }
            uint2 frag = make_uint2(packh(p[0], p[1]), packh(p[2], p[3]));
            if (idx < ZRE) g_BfZr[e] = frag; else g_BfC[e] = frag;
        }
    }
}

// ---------------- aggregation: 2 nodes/block, fp16x2 gathers, fp32 accumulate ----------
__global__ void __launch_bounds__(256) agg_kernel(const float* __restrict__ x_dis, int t, int full) {
    const __half* __restrict__ hb = full ? g_hb : g_rhb;    // fp16 source (direct + gathers)
    int tid = threadIdx.x;
    int nl = tid >> 7, b = (tid >> 5) & 3, cp = tid & 31;
    int c  = cp * 2;
    int n  = blockIdx.x*2 + nl;
    int row = n*BATCH + b;
    size_t ub = (size_t)row * KDIM;
    const float* __restrict__ xb = x_dis + (size_t)(b*T_STEPS + t)*N_NODES;

    // direct channels (fp16 mirror == fp16(fp32 value): bit-identical U)
    {
        __half2 dv = *(const __half2*)&hb[row*HID + c];
        g_U[ub + 1 + c]     = __low2half(dv);
        g_U[ub + 1 + c + 1] = __high2half(dv);
    }
    if (full && cp == 0) g_U[ub] = __float2half(xb[n]);

    for (int dir = 0; dir < 2; dir++) {
        const int*   off = dir == 0 ? g_offF : g_offB;
        const int*   src = dir == 0 ? g_srcF : g_srcB;
        const float* ww  = dir == 0 ? g_wF   : g_wB;
        int e0 = off[n], e1 = off[n + 1];
        float a0 = 0.f, a1 = 0.f, ax = 0.f;
        int e = e0;
        for (; e + 4 <= e1; e += 4) {
            int s0 = src[e], s1 = src[e+1], s2 = src[e+2], s3 = src[e+3];
            float w0 = ww[e], w1 = ww[e+1], w2 = ww[e+2], w3 = ww[e+3];
            __half2 v0 = *(const __half2*)&hb[(s0*BATCH+b)*HID + c];
            __half2 v1 = *(const __half2*)&hb[(s1*BATCH+b)*HID + c];
            __half2 v2 = *(const __half2*)&hb[(s2*BATCH+b)*HID + c];
            __half2 v3 = *(const __half2*)&hb[(s3*BATCH+b)*HID + c];
            a0 += w0*__low2float(v0)  + w1*__low2float(v1)
                + w2*__low2float(v2)  + w3*__low2float(v3);
            a1 += w0*__high2float(v0) + w1*__high2float(v1)
                + w2*__high2float(v2) + w3*__high2float(v3);
            if (full && cp == 0)
                ax += w0*xb[s0] + w1*xb[s1] + w2*xb[s2] + w3*xb[s3];
        }
        for (; e < e1; e++) {
            int s = src[e]; float w = ww[e];
            __half2 v = *(const __half2*)&hb[(s*BATCH+b)*HID + c];
            a0 += w*__low2float(v);
            a1 += w*__high2float(v);
            if (full && cp == 0) ax += w*xb[s];
        }
        int chbase = dir == 0 ? 65 : 130;
        g_U[ub + chbase + 1 + c]     = __float2half(a0);
        g_U[ub + chbase + 1 + c + 1] = __float2half(a1);
        if (full && cp == 0) g_U[ub + chbase] = __float2half(ax);
    }
}

// ---------------- HMMA GEMM (fp16 A, fp16 hi/lo B), 1m x 8n warp layout ----------
__device__ __forceinline__ void mma16816(float* d, const u32* a, const u32* b) {
    asm volatile("mma.sync.aligned.m16n8k16.row.col.f32.f16.f16.f32 "
        "{%0,%1,%2,%3}, {%4,%5,%6,%7}, {%8,%9}, {%0,%1,%2,%3};"
        : "+f"(d[0]), "+f"(d[1]), "+f"(d[2]), "+f"(d[3])
        : "r"(a[0]), "r"(a[1]), "r"(a[2]), "r"(a[3]), "r"(b[0]), "r"(b[1]));
}
__device__ __forceinline__ void ldmx4(u32* r, u32 addr) {
    asm volatile("ldmatrix.sync.aligned.m8n8.x4.shared.b16 {%0,%1,%2,%3}, [%4];"
        : "=r"(r[0]), "=r"(r[1]), "=r"(r[2]), "=r"(r[3]) : "r"(addr));
}
__device__ __forceinline__ float sigf(float v) { return 1.f / (1.f + __expf(-v)); }

// BM=64, 256 threads = 8 warps, ALL warps span the 64 rows; warp wid owns
// cols [wid*NOUT/8, (wid+1)*NOUT/8). B table read exactly once per block.
template<int NOUT>
__global__ void __launch_bounds__(256) gemm_kernel() {
    constexpr int NATOT = NOUT / 8;
    constexpr int NA    = NOUT / 64;          // natoms per warp (2 for 128, 1 for 64)
    constexpr int WCOL  = NOUT / 8;           // cols per warp

    extern __shared__ __half sA[];            // [64][SPITCH]
    int tid = threadIdx.x;
    int rowBase = blockIdx.x * 64;

    // stage A: 64 rows x 208 cols fp16 = 1664 uint4, coalesced
#pragma unroll
    for (int q = 0; q < 7; q++) {
        int idx = tid + q*256;
        if (idx < 1664) {
            int r = idx / 26, c8 = idx % 26;
            uint4 v = *(const uint4*)(g_U + (size_t)(rowBase + r)*KDIM + c8*8);
            *(uint4*)(sA + r*SPITCH + c8*8) = v;
        }
    }
    __syncthreads();

    int wid = tid >> 5, lane = tid & 31;
    const uint2* __restrict__ Bf = (NOUT == 128) ? g_BfZr : g_BfC;

    u32 aBase = smem_u32(sA);
    int rloc = lane & 15;
    u32 csel = (u32)(lane >> 4) * 16;

    float acc[4][NA][4];
#pragma unroll
    for (int ma = 0; ma < 4; ma++)
#pragma unroll
        for (int j = 0; j < NA; j++)
#pragma unroll
            for (int q = 0; q < 4; q++) acc[ma][j][q] = 0.f;

#pragma unroll 1
    for (int ks = 0; ks < NKS; ks++) {
        u32 kb = (u32)ks * 32;
        u32 a[4][4];
#pragma unroll
        for (int ma = 0; ma < 4; ma++) {
            u32 off = (u32)(rloc + ma*16) * (SPITCH*2) + kb + csel;
            ldmx4(a[ma], aBase + off);
        }
        uint2 bh[NA], bl[NA];
#pragma unroll
        for (int j = 0; j < NA; j++) {
            int na = wid*NA + j;
            bh[j] = Bf[((ks*2 + 0)*NATOT + na)*32 + lane];
            bl[j] = Bf[((ks*2 + 1)*NATOT + na)*32 + lane];
        }
#pragma unroll
        for (int ma = 0; ma < 4; ma++)
#pragma unroll
            for (int j = 0; j < NA; j++) {
                mma16816(acc[ma][j], a[ma], (const u32*)&bh[j]);
                mma16816(acc[ma][j], a[ma], (const u32*)&bl[j]);
            }
    }

    // epilogue (maintains fp16 mirrors; rh exists ONLY as fp16)
    int rbase = rowBase + (lane >> 2);
#pragma unroll
    for (int ma = 0; ma < 4; ma++) {
#pragma unroll
        for (int j = 0; j < NA; j++) {
            int col = wid*WCOL + j*8 + (lane & 3)*2;
#pragma unroll
            for (int half = 0; half < 2; half++) {
                int row = rbase + ma*16 + half*8;
                float d0 = acc[ma][j][half*2], d1 = acc[ma][j][half*2 + 1];
                if (NOUT == 128) {
                    if (col < 64) {
                        float2 zv = make_float2(sigf(d0 + g_bzr[col]), sigf(d1 + g_bzr[col+1]));
                        *(float2*)&g_z[row*HID + col] = zv;
                    } else {
                        int jr = col - 64;
                        float2 hv = *(const float2*)&g_h[row*HID + jr];
                        float rv0 = sigf(d0 + g_bzr[col]) * hv.x;
                        float rv1 = sigf(d1 + g_bzr[col+1]) * hv.y;
                        *(__half2*)&g_rhb[row*HID + jr] = __floats2half2_rn(rv0, rv1);
                    }
                } else {
                    float c0 = tanhf(d0 + g_bh[col]);
                    float c1 = tanhf(d1 + g_bh[col+1]);
                    float2 zv = *(const float2*)&g_z[row*HID + col];
                    float2 hv = *(const float2*)&g_h[row*HID + col];
                    float2 nh = make_float2(zv.x*hv.x + (1.f - zv.x)*c0,
                                            zv.y*hv.y + (1.f - zv.y)*c1);
                    *(float2*)&g_h[row*HID + col] = nh;
                    *(__half2*)&g_hb[row*HID + col] = __floats2half2_rn(nh.x, nh.y);
                }
            }
        }
    }
}

// ---------------- readout (node 0 only) ----------------
__global__ void readout_kernel(const float* __restrict__ W1, const float* __restrict__ b1,
                               const float* __restrict__ W2, const float* __restrict__ b2,
                               float* __restrict__ out) {
    int tid = threadIdx.x;
    int b = tid >> 6, j = tid & 63;
    float acc = b1[j];
#pragma unroll
    for (int c = 0; c < HID; c++)
        acc += g_h[b*HID + c] * W1[c*HID + j];
    float v = fmaxf(acc, 0.f) * W2[j];
#pragma unroll
    for (int o = 16; o > 0; o >>= 1) v += __shfl_down_sync(0xffffffff, v, o);
    __shared__ float part[8];
    if ((tid & 31) == 0) part[tid >> 5] = v;
    __syncthreads();
    if (j == 0) out[b] = part[b*2] + part[b*2 + 1] + b2[0];
}

// ---------------- launch ----------------
extern "C" void kernel_launch(void* const* d_in, const int* in_sizes, int n_in,
                              void* d_out, int out_size) {
    const float* x_dis = (const float*)d_in[0];
    const int*   ei    = (const int*)  d_in[1];
    const float* ew    = (const float*)d_in[2];
    const float* W_z   = (const float*)d_in[3];
    const float* b_z   = (const float*)d_in[4];
    const float* W_r   = (const float*)d_in[5];
    const float* b_r   = (const float*)d_in[6];
    const float* W_h   = (const float*)d_in[7];
    const float* b_h   = (const float*)d_in[8];
    const float* W_ro1 = (const float*)d_in[9];
    const float* b_ro1 = (const float*)d_in[10];
    const float* W_ro2 = (const float*)d_in[11];
    const float* b_ro2 = (const float*)d_in[12];
    float* out = (float*)d_out;

    const int PREP_SMEM = 4 * 10240 * 4;                 // 160 KB
    const int GEMM_SMEM = 64 * SPITCH * 2;               // 27648 B
    cudaFuncSetAttribute(prep_scan, cudaFuncAttributeMaxDynamicSharedMemorySize, PREP_SMEM);
    cudaFuncSetAttribute(gemm_kernel<128>, cudaFuncAttributeMaxDynamicSharedMemorySize, GEMM_SMEM);
    cudaFuncSetAttribute(gemm_kernel<64>,  cudaFuncAttributeMaxDynamicSharedMemorySize, GEMM_SMEM);

    prep_scan<<<1, 1024, PREP_SMEM>>>(ei, ew);
    fill_misc<<<FILL_BLKS + ZEROH_BLKS + BFRAG_BLKS, 256>>>(ei, ew, W_z, b_z, W_r, b_r, W_h, b_h);

    for (int t = 0; t < T_STEPS; t++) {
        agg_kernel<<<N_NODES/2, 256>>>(x_dis, t, 1);
        gemm_kernel<128><<<M_PAD/64, 256, GEMM_SMEM>>>();
        agg_kernel<<<N_NODES/2, 256>>>(x_dis, t, 0);
        gemm_kernel<64><<<M_PAD/64, 256, GEMM_SMEM>>>();
    }
    readout_kernel<<<1, 256>>>(W_ro1, b_ro1, W_ro2, b_ro2, out);
}

// round 12
// speedup vs baseline: 3.2243x; 1.2937x over previous
#include <cuda_runtime.h>
#include <cuda_fp16.h>
#include <stdint.h>
#include <math.h>

#define N_NODES 10000
#define N_EDGES 160000
#define BATCH 4
#define T_STEPS 16
#define HID 64
#define M_PAD  40064             // 626 * 64
#define KDIM 208                 // 13 * 16
#define NKS 13
#define SPITCH 216               // smem A pitch in halves (432B: conflict-free ldmatrix)

typedef uint32_t u32;

// U channel layout (K axis, permuted for aligned agg stores):
//   [0..63]   = h | rh      (direct)
//   [64..127] = aggF(h|rh)
//   [128..191]= aggB(h|rh)
//   [192]=x  [193]=aggF_x  [194]=aggB_x
//   [195..207]= 0 (pad)
// The permutation is folded into the B fragment tables at build time.

// ---------------- device scratch ----------------
__device__ float g_h [M_PAD*HID];
__device__ float g_z [M_PAD*HID];
__device__ __align__(16) __half g_hb [M_PAD*HID];   // fp16 mirror of h
__device__ __align__(16) __half g_rhb[M_PAD*HID];   // fp16 rh (only representation)
__device__ __align__(16) __half g_U  [(size_t)M_PAD*KDIM];   // fp16 activations (GEMM A)
__device__ float g_deg_out[N_NODES], g_deg_in[N_NODES];
__device__ int   g_cntF[N_NODES], g_cntB[N_NODES];
__device__ int   g_offF[N_NODES+1], g_offB[N_NODES+1];
__device__ int   g_srcF[N_EDGES], g_srcB[N_EDGES];
__device__ float g_wF[N_EDGES],  g_wB[N_EDGES];
// Prepacked B fragment tables (fp16 hi/lo): [ks][split][natom][lane] -> uint2
__device__ uint2 g_BfZr[NKS*2*16*32];
__device__ uint2 g_BfC [NKS*2*8*32];
__device__ float g_bzr[128], g_bh[64];

__device__ __forceinline__ u32 smem_u32(const void* p) {
    u32 a;
    asm("{ .reg .u64 t; cvta.to.shared.u64 t, %1; cvt.u32.u64 %0, t; }" : "=r"(a) : "l"(p));
    return a;
}

// ---------------- prep 1: single-block histogram + degree + scan ----------------
__global__ void prep_scan(const int* __restrict__ ei, const float* __restrict__ ew) {
    extern __shared__ int sm[];
    int*   cF = sm;
    int*   cB = sm + 10240;
    float* dF = (float*)(sm + 20480);
    float* dB = (float*)(sm + 30720);
    __shared__ int sb[1024];
    int t = threadIdx.x;

    for (int i = t; i < 10240; i += 1024) { cF[i]=0; cB[i]=0; dF[i]=0.f; dB[i]=0.f; }
    __syncthreads();

    for (int e = t; e < N_EDGES; e += 1024) {
        int r = ei[e], c = ei[N_EDGES + e];
        float w = ew[e];
        atomicAdd(&cF[r], 1);
        atomicAdd(&cB[c], 1);
        atomicAdd(&dF[r], w);
        atomicAdd(&dB[c], w);
    }
    __syncthreads();

    for (int i = t; i < N_NODES; i += 1024) {
        g_deg_out[i] = dF[i];
        g_deg_in [i] = dB[i];
        g_cntF[i] = 0;
        g_cntB[i] = 0;
    }

    for (int pass = 0; pass < 2; pass++) {
        const int* cnt = pass == 0 ? cF : cB;
        int*       off = pass == 0 ? g_offF : g_offB;
        int carry = 0;
        for (int base = 0; base < N_NODES; base += 1024) {
            int v = (base + t < N_NODES) ? cnt[base + t] : 0;
            sb[t] = v; __syncthreads();
            for (int o = 1; o < 1024; o <<= 1) {
                int y = (t >= o) ? sb[t - o] : 0;
                __syncthreads();
                sb[t] += y;
                __syncthreads();
            }
            if (base + t < N_NODES) off[base + t] = carry + sb[t] - v;
            carry += sb[1023];
            __syncthreads();
        }
        if (t == 0) off[N_NODES] = carry;
        __syncthreads();
    }
}

// ---------------- prep 2: edge fill + zero h + B fragment build ----------------
#define FILL_BLKS 625
#define ZEROH_BLKS 10016          // M_PAD*HID/256
#define ZRE (NKS*2*16*32)         // 13312
#define CE  (NKS*2*8*32)          // 6656
#define BFRAG_BLKS 78

// wval over the ORIGINAL channel indexing: [0]=x,[1..64]=h,[65]=aggFx,[66..129]=aggFh,
// [130]=aggBx,[131..194]=aggBh, >=195 pad.
__device__ __forceinline__ float wval(const float* W, int c, int j) {
    if (c >= 195) return 0.f;
    if (c < 65)  return W[(0*65 + c)*64 + j] + W[(2*65 + c)*64 + j];
    if (c < 130) return W[(1*65 + (c-65))*64 + j];
    return W[(3*65 + (c-130))*64 + j];
}
// map NEW (permuted) channel -> ORIGINAL channel
__device__ __forceinline__ int newc(int c) {
    if (c < 64)  return c + 1;        // h
    if (c < 128) return c + 2;        // aggF_h
    if (c < 192) return c + 3;        // aggB_h
    if (c == 192) return 0;           // x
    if (c == 193) return 65;          // aggF_x
    if (c == 194) return 130;         // aggB_x
    return 999;                        // pad -> 0
}
__device__ __forceinline__ u32 packh(float a, float b) {
    __half2 t = __floats2half2_rn(a, b);
    return *(u32*)&t;
}
__global__ void fill_misc(const int* __restrict__ ei, const float* __restrict__ ew,
                          const float* __restrict__ Wz, const float* __restrict__ bz,
                          const float* __restrict__ Wr, const float* __restrict__ br,
                          const float* __restrict__ Wh, const float* __restrict__ bh) {
    int blk = blockIdx.x, tid = threadIdx.x;
    if (blk < FILL_BLKS) {
        int e = blk*256 + tid;
        if (e >= N_EDGES) return;
        int r = ei[e], c = ei[N_EDGES + e];
        float w = ew[e];
        float dof = g_deg_out[r];
        float cf = (dof > 0.f) ? w / dof : 0.f;
        int p = g_offF[r] + atomicAdd(&g_cntF[r], 1);
        g_srcF[p] = c; g_wF[p] = cf;
        float din = g_deg_in[c];
        float cb = (din > 0.f) ? w / din : 0.f;
        int q = g_offB[c] + atomicAdd(&g_cntB[c], 1);
        g_srcB[q] = r; g_wB[q] = cb;
    } else if (blk < FILL_BLKS + ZEROH_BLKS) {
        int i = (blk - FILL_BLKS)*256 + tid;
        if (i < M_PAD*HID) { g_h[i] = 0.f; g_hb[i] = __float2half(0.f); }
    } else {
        int idx = (blk - FILL_BLKS - ZEROH_BLKS)*256 + tid;
        if (idx < 128) g_bzr[idx] = (idx < 64) ? bz[idx] : br[idx - 64];
        if (idx < 64)  g_bh[idx] = bh[idx];
        if (idx < ZRE + CE) {
            int natot = (idx < ZRE) ? 16 : 8;
            int e = (idx < ZRE) ? idx : idx - ZRE;
            int lane = e & 31;
            int na   = (e >> 5) % natot;
            int split = (e / (32*natot)) & 1;
            int ks    = e / (64*natot);
            int k0 = ks*16 + (lane & 3)*2;
            int n  = na*8 + (lane >> 2);
            float v[4];
            if (idx < ZRE) {
                const float* W = (n < 64) ? Wz : Wr;
                int j = n & 63;
                v[0] = wval(W, newc(k0),   j); v[1] = wval(W, newc(k0+1), j);
                v[2] = wval(W, newc(k0+8), j); v[3] = wval(W, newc(k0+9), j);
            } else {
                v[0] = wval(Wh, newc(k0),   n); v[1] = wval(Wh, newc(k0+1), n);
                v[2] = wval(Wh, newc(k0+8), n); v[3] = wval(Wh, newc(k0+9), n);
            }
            float p[4];
            for (int i2 = 0; i2 < 4; i2++) {
                float hi = __half2float(__float2half(v[i2]));
                p[i2] = split ? (v[i2] - hi) : hi;
            }
            uint2 frag = make_uint2(packh(p[0], p[1]), packh(p[2], p[3]));
            if (idx < ZRE) g_BfZr[e] = frag; else g_BfC[e] = frag;
        }
    }
}

// ---------------- aggregation: 4 nodes/block, fp16x4 (uint2) gathers ----------
__global__ void __launch_bounds__(256) agg_kernel(const float* __restrict__ x_dis, int t, int full) {
    const __half* __restrict__ hb = full ? g_hb : g_rhb;    // fp16 source (direct + gathers)
    int tid = threadIdx.x;
    int nl = tid >> 6, b = (tid >> 4) & 3, cp = tid & 15;
    int c  = cp * 4;
    int n  = blockIdx.x*4 + nl;
    int row = n*BATCH + b;
    size_t ub = (size_t)row * KDIM;
    const float* __restrict__ xb = x_dis + (size_t)(b*T_STEPS + t)*N_NODES;

    // direct channels: aligned 8B copy from fp16 mirror (bit-identical to fp16(fp32))
    *(uint2*)&g_U[ub + c] = *(const uint2*)&hb[row*HID + c];
    if (full && cp == 0) g_U[ub + 192] = __float2half(xb[n]);

    for (int dir = 0; dir < 2; dir++) {
        const int*   off = dir == 0 ? g_offF : g_offB;
        const int*   src = dir == 0 ? g_srcF : g_srcB;
        const float* ww  = dir == 0 ? g_wF   : g_wB;
        int e0 = off[n], e1 = off[n + 1];
        float a0 = 0.f, a1 = 0.f, a2 = 0.f, a3 = 0.f, ax = 0.f;
        int e = e0;
        for (; e + 4 <= e1; e += 4) {
            int s0 = src[e], s1 = src[e+1], s2 = src[e+2], s3 = src[e+3];
            float w0 = ww[e], w1 = ww[e+1], w2 = ww[e+2], w3 = ww[e+3];
            uint2 u0 = *(const uint2*)&hb[(s0*BATCH+b)*HID + c];
            uint2 u1 = *(const uint2*)&hb[(s1*BATCH+b)*HID + c];
            uint2 u2 = *(const uint2*)&hb[(s2*BATCH+b)*HID + c];
            uint2 u3 = *(const uint2*)&hb[(s3*BATCH+b)*HID + c];
            __half2 p00 = *(__half2*)&u0.x, p01 = *(__half2*)&u0.y;
            __half2 p10 = *(__half2*)&u1.x, p11 = *(__half2*)&u1.y;
            __half2 p20 = *(__half2*)&u2.x, p21 = *(__half2*)&u2.y;
            __half2 p30 = *(__half2*)&u3.x, p31 = *(__half2*)&u3.y;
            a0 += w0*__low2float(p00)  + w1*__low2float(p10)  + w2*__low2float(p20)  + w3*__low2float(p30);
            a1 += w0*__high2float(p00) + w1*__high2float(p10) + w2*__high2float(p20) + w3*__high2float(p30);
            a2 += w0*__low2float(p01)  + w1*__low2float(p11)  + w2*__low2float(p21)  + w3*__low2float(p31);
            a3 += w0*__high2float(p01) + w1*__high2float(p11) + w2*__high2float(p21) + w3*__high2float(p31);
            if (full && cp == 0)
                ax += w0*xb[s0] + w1*xb[s1] + w2*xb[s2] + w3*xb[s3];
        }
        for (; e < e1; e++) {
            int s = src[e]; float w = ww[e];
            uint2 u = *(const uint2*)&hb[(s*BATCH+b)*HID + c];
            __half2 p0 = *(__half2*)&u.x, p1 = *(__half2*)&u.y;
            a0 += w*__low2float(p0);
            a1 += w*__high2float(p0);
            a2 += w*__low2float(p1);
            a3 += w*__high2float(p1);
            if (full && cp == 0) ax += w*xb[s];
        }
        int chbase = dir == 0 ? 64 : 128;
        uint2 st;
        st.x = packh(a0, a1);
        st.y = packh(a2, a3);
        *(uint2*)&g_U[ub + chbase + c] = st;
        if (full && cp == 0) g_U[ub + 193 + dir] = __float2half(ax);
    }
}

// ---------------- HMMA GEMM (fp16 A, fp16 hi/lo B), 1m x 8n warp layout ----------
__device__ __forceinline__ void mma16816(float* d, const u32* a, const u32* b) {
    asm volatile("mma.sync.aligned.m16n8k16.row.col.f32.f16.f16.f32 "
        "{%0,%1,%2,%3}, {%4,%5,%6,%7}, {%8,%9}, {%0,%1,%2,%3};"
        : "+f"(d[0]), "+f"(d[1]), "+f"(d[2]), "+f"(d[3])
        : "r"(a[0]), "r"(a[1]), "r"(a[2]), "r"(a[3]), "r"(b[0]), "r"(b[1]));
}
__device__ __forceinline__ void ldmx4(u32* r, u32 addr) {
    asm volatile("ldmatrix.sync.aligned.m8n8.x4.shared.b16 {%0,%1,%2,%3}, [%4];"
        : "=r"(r[0]), "=r"(r[1]), "=r"(r[2]), "=r"(r[3]) : "r"(addr));
}
__device__ __forceinline__ float sigf(float v) { return 1.f / (1.f + __expf(-v)); }

// BM=64, 256 threads = 8 warps, ALL warps span the 64 rows; warp wid owns
// cols [wid*NOUT/8, (wid+1)*NOUT/8). B table read exactly once per block.
template<int NOUT>
__global__ void __launch_bounds__(256) gemm_kernel() {
    constexpr int NATOT = NOUT / 8;
    constexpr int NA    = NOUT / 64;          // natoms per warp (2 for 128, 1 for 64)
    constexpr int WCOL  = NOUT / 8;           // cols per warp

    extern __shared__ __half sA[];            // [64][SPITCH]
    int tid = threadIdx.x;
    int rowBase = blockIdx.x * 64;

    // stage A: 64 rows x 208 cols fp16 = 1664 uint4, coalesced
#pragma unroll
    for (int q = 0; q < 7; q++) {
        int idx = tid + q*256;
        if (idx < 1664) {
            int r = idx / 26, c8 = idx % 26;
            uint4 v = *(const uint4*)(g_U + (size_t)(rowBase + r)*KDIM + c8*8);
            *(uint4*)(sA + r*SPITCH + c8*8) = v;
        }
    }
    __syncthreads();

    int wid = tid >> 5, lane = tid & 31;
    const uint2* __restrict__ Bf = (NOUT == 128) ? g_BfZr : g_BfC;

    u32 aBase = smem_u32(sA);
    int rloc = lane & 15;
    u32 csel = (u32)(lane >> 4) * 16;

    float acc[4][NA][4];
#pragma unroll
    for (int ma = 0; ma < 4; ma++)
#pragma unroll
        for (int j = 0; j < NA; j++)
#pragma unroll
            for (int q = 0; q < 4; q++) acc[ma][j][q] = 0.f;

#pragma unroll 1
    for (int ks = 0; ks < NKS; ks++) {
        u32 kb = (u32)ks * 32;
        u32 a[4][4];
#pragma unroll
        for (int ma = 0; ma < 4; ma++) {
            u32 off = (u32)(rloc + ma*16) * (SPITCH*2) + kb + csel;
            ldmx4(a[ma], aBase + off);
        }
        uint2 bh[NA], bl[NA];
#pragma unroll
        for (int j = 0; j < NA; j++) {
            int na = wid*NA + j;
            bh[j] = Bf[((ks*2 + 0)*NATOT + na)*32 + lane];
            bl[j] = Bf[((ks*2 + 1)*NATOT + na)*32 + lane];
        }
#pragma unroll
        for (int ma = 0; ma < 4; ma++)
#pragma unroll
            for (int j = 0; j < NA; j++) {
                mma16816(acc[ma][j], a[ma], (const u32*)&bh[j]);
                mma16816(acc[ma][j], a[ma], (const u32*)&bl[j]);
            }
    }

    // epilogue (maintains fp16 mirrors; rh exists ONLY as fp16)
    int rbase = rowBase + (lane >> 2);
#pragma unroll
    for (int ma = 0; ma < 4; ma++) {
#pragma unroll
        for (int j = 0; j < NA; j++) {
            int col = wid*WCOL + j*8 + (lane & 3)*2;
#pragma unroll
            for (int half = 0; half < 2; half++) {
                int row = rbase + ma*16 + half*8;
                float d0 = acc[ma][j][half*2], d1 = acc[ma][j][half*2 + 1];
                if (NOUT == 128) {
                    if (col < 64) {
                        float2 zv = make_float2(sigf(d0 + g_bzr[col]), sigf(d1 + g_bzr[col+1]));
                        *(float2*)&g_z[row*HID + col] = zv;
                    } else {
                        int jr = col - 64;
                        float2 hv = *(const float2*)&g_h[row*HID + jr];
                        float rv0 = sigf(d0 + g_bzr[col]) * hv.x;
                        float rv1 = sigf(d1 + g_bzr[col+1]) * hv.y;
                        *(__half2*)&g_rhb[row*HID + jr] = __floats2half2_rn(rv0, rv1);
                    }
                } else {
                    float c0 = tanhf(d0 + g_bh[col]);
                    float c1 = tanhf(d1 + g_bh[col+1]);
                    float2 zv = *(const float2*)&g_z[row*HID + col];
                    float2 hv = *(const float2*)&g_h[row*HID + col];
                    float2 nh = make_float2(zv.x*hv.x + (1.f - zv.x)*c0,
                                            zv.y*hv.y + (1.f - zv.y)*c1);
                    *(float2*)&g_h[row*HID + col] = nh;
                    *(__half2*)&g_hb[row*HID + col] = __floats2half2_rn(nh.x, nh.y);
                }
            }
        }
    }
}

// ---------------- readout (node 0 only) ----------------
__global__ void readout_kernel(const float* __restrict__ W1, const float* __restrict__ b1,
                               const float* __restrict__ W2, const float* __restrict__ b2,
                               float* __restrict__ out) {
    int tid = threadIdx.x;
    int b = tid >> 6, j = tid & 63;
    float acc = b1[j];
#pragma unroll
    for (int c = 0; c < HID; c++)
        acc += g_h[b*HID + c] * W1[c*HID + j];
    float v = fmaxf(acc, 0.f) * W2[j];
#pragma unroll
    for (int o = 16; o > 0; o >>= 1) v += __shfl_down_sync(0xffffffff, v, o);
    __shared__ float part[8];
    if ((tid & 31) == 0) part[tid >> 5] = v;
    __syncthreads();
    if (j == 0) out[b] = part[b*2] + part[b*2 + 1] + b2[0];
}

// ---------------- launch ----------------
extern "C" void kernel_launch(void* const* d_in, const int* in_sizes, int n_in,
                              void* d_out, int out_size) {
    const float* x_dis = (const float*)d_in[0];
    const int*   ei    = (const int*)  d_in[1];
    const float* ew    = (const float*)d_in[2];
    const float* W_z   = (const float*)d_in[3];
    const float* b_z   = (const float*)d_in[4];
    const float* W_r   = (const float*)d_in[5];
    const float* b_r   = (const float*)d_in[6];
    const float* W_h   = (const float*)d_in[7];
    const float* b_h   = (const float*)d_in[8];
    const float* W_ro1 = (const float*)d_in[9];
    const float* b_ro1 = (const float*)d_in[10];
    const float* W_ro2 = (const float*)d_in[11];
    const float* b_ro2 = (const float*)d_in[12];
    float* out = (float*)d_out;

    const int PREP_SMEM = 4 * 10240 * 4;                 // 160 KB
    const int GEMM_SMEM = 64 * SPITCH * 2;               // 27648 B
    cudaFuncSetAttribute(prep_scan, cudaFuncAttributeMaxDynamicSharedMemorySize, PREP_SMEM);
    cudaFuncSetAttribute(gemm_kernel<128>, cudaFuncAttributeMaxDynamicSharedMemorySize, GEMM_SMEM);
    cudaFuncSetAttribute(gemm_kernel<64>,  cudaFuncAttributeMaxDynamicSharedMemorySize, GEMM_SMEM);

    prep_scan<<<1, 1024, PREP_SMEM>>>(ei, ew);
    fill_misc<<<FILL_BLKS + ZEROH_BLKS + BFRAG_BLKS, 256>>>(ei, ew, W_z, b_z, W_r, b_r, W_h, b_h);

    for (int t = 0; t < T_STEPS; t++) {
        agg_kernel<<<N_NODES/4, 256>>>(x_dis, t, 1);
        gemm_kernel<128><<<M_PAD/64, 256, GEMM_SMEM>>>();
        agg_kernel<<<N_NODES/4, 256>>>(x_dis, t, 0);
        gemm_kernel<64><<<M_PAD/64, 256, GEMM_SMEM>>>();
    }
    readout_kernel<<<1, 256>>>(W_ro1, b_ro1, W_ro2, b_ro2, out);
}